// round 1
// baseline (speedup 1.0000x reference)
#include <cuda_runtime.h>
#include <math.h>

// Problem constants
constexpr int BATCH = 2;
constexpr int SEQ   = 2048;
constexpr int DIMV  = 2048;
constexpr int NH    = 16;
constexpr int HDIM  = 128;          // head dim
constexpr int MROWS = BATCH * SEQ;  // 4096
constexpr float QSCALE = 0.08838834764831845f;  // 1/sqrt(128)

// Scratch (device-global; no runtime allocation allowed)
__device__ float g_q [MROWS * DIMV];
__device__ float g_k [MROWS * DIMV];
__device__ float g_v [MROWS * DIMV];
__device__ float g_ao[MROWS * DIMV];

// ---------------------------------------------------------------------------
// SGEMM: C[M,N] = A[M,K] @ W[K,N], M=4096, N=2048, K=2048, fp32
// 128x128 block tile, BK=16, 8x8 per-thread microtile, 256 threads
// ---------------------------------------------------------------------------
constexpr int GBM = 128, GBN = 128, GBK = 16, GTM = 8, GTN = 8;

__device__ __forceinline__ void sgemm_body(const float* __restrict__ A,
                                           const float* __restrict__ W,
                                           float* __restrict__ C)
{
    constexpr int N = DIMV;
    constexpr int K = DIMV;

    __shared__ float As[GBK][GBM + 4];   // stored transposed: As[k][m]
    __shared__ float Bs[GBK][GBN + 4];

    const int tid  = threadIdx.x;
    const int brow = blockIdx.y * GBM;
    const int bcol = blockIdx.x * GBN;
    const int ty   = tid >> 4;          // 0..15
    const int tx   = tid & 15;          // 0..15

    // load index precompute
    const int ar = tid >> 2;            // 0..63  (A rows, 2 halves)
    const int ac = (tid & 3) * 4;       // 0,4,8,12
    const int br = tid >> 5;            // 0..7   (W rows, 2 halves)
    const int bc = (tid & 31) * 4;      // 0..124

    float acc[GTM][GTN] = {};

    for (int k0 = 0; k0 < K; k0 += GBK) {
        #pragma unroll
        for (int half = 0; half < 2; half++) {
            const int r = ar + half * 64;
            float4 a = *(const float4*)(A + (size_t)(brow + r) * K + k0 + ac);
            As[ac + 0][r] = a.x;
            As[ac + 1][r] = a.y;
            As[ac + 2][r] = a.z;
            As[ac + 3][r] = a.w;
        }
        #pragma unroll
        for (int half = 0; half < 2; half++) {
            const int r = br + half * 8;
            *(float4*)(&Bs[r][bc]) =
                *(const float4*)(W + (size_t)(k0 + r) * N + bcol + bc);
        }
        __syncthreads();

        #pragma unroll
        for (int k = 0; k < GBK; k++) {
            float4 a0 = *(const float4*)(&As[k][ty * GTM]);
            float4 a1 = *(const float4*)(&As[k][ty * GTM + 4]);
            float4 b0 = *(const float4*)(&Bs[k][tx * GTN]);
            float4 b1 = *(const float4*)(&Bs[k][tx * GTN + 4]);
            float ra[8] = {a0.x, a0.y, a0.z, a0.w, a1.x, a1.y, a1.z, a1.w};
            float rb[8] = {b0.x, b0.y, b0.z, b0.w, b1.x, b1.y, b1.z, b1.w};
            #pragma unroll
            for (int i = 0; i < GTM; i++)
                #pragma unroll
                for (int j = 0; j < GTN; j++)
                    acc[i][j] = fmaf(ra[i], rb[j], acc[i][j]);
        }
        __syncthreads();
    }

    #pragma unroll
    for (int i = 0; i < GTM; i++) {
        float4* cp = (float4*)(C + (size_t)(brow + ty * GTM + i) * N + bcol + tx * GTN);
        cp[0] = make_float4(acc[i][0], acc[i][1], acc[i][2], acc[i][3]);
        cp[1] = make_float4(acc[i][4], acc[i][5], acc[i][6], acc[i][7]);
    }
}

__global__ __launch_bounds__(256) void qkv_kernel(const float* __restrict__ x,
                                                  const float* __restrict__ wq,
                                                  const float* __restrict__ wk,
                                                  const float* __restrict__ wv)
{
    const float* w   = (blockIdx.z == 0) ? wq : (blockIdx.z == 1) ? wk : wv;
    float*       out = (blockIdx.z == 0) ? g_q : (blockIdx.z == 1) ? g_k : g_v;
    sgemm_body(x, w, out);
}

__global__ __launch_bounds__(256) void oproj_kernel(const float* __restrict__ wo,
                                                    float* __restrict__ out)
{
    sgemm_body(g_ao, wo, out);
}

// ---------------------------------------------------------------------------
// RoPE on Q (with q-scale folded in) and K, in place.
// pair index p: d fastest (HD/2=64), then h (16), then s (2048), then b (2)
// ---------------------------------------------------------------------------
__global__ __launch_bounds__(256) void rope_kernel(const float* __restrict__ cs,
                                                   const float* __restrict__ sn)
{
    const int p = blockIdx.x * blockDim.x + threadIdx.x;   // 0 .. 2^22-1
    const int d = p & 63;
    const int h = (p >> 6) & (NH - 1);
    const int s = (p >> 10) & (SEQ - 1);
    const int b = p >> 21;

    const float c = cs[s * 64 + d];
    const float si = sn[s * 64 + d];

    const size_t off = (size_t)(b * SEQ + s) * DIMV + h * HDIM + 2 * d;

    float qr = g_q[off], qi = g_q[off + 1];
    g_q[off]     = (qr * c - qi * si) * QSCALE;
    g_q[off + 1] = (qr * si + qi * c) * QSCALE;

    float kr = g_k[off], ki = g_k[off + 1];
    g_k[off]     = kr * c - ki * si;
    g_k[off + 1] = kr * si + ki * c;
}

// ---------------------------------------------------------------------------
// Flash-style causal attention, fp32.
// Block: one (b,h) x 64 q-rows. 256 threads.
// ---------------------------------------------------------------------------
constexpr int FBQ = 64;    // q rows per block
constexpr int FBK = 64;    // kv rows per tile

struct FlashSmem {
    float Qt[HDIM][FBQ + 4];   // Q transposed: [k][row]
    float Kt[HDIM][FBK + 4];   // K transposed: [k][col]
    float Vs[FBK][HDIM];       // V natural
    float Ss[FBQ][FBK + 4];    // scores / probs
    float m_s[FBQ];
    float l_s[FBQ];
    float sc_s[FBQ];
};

__global__ __launch_bounds__(256) void flash_kernel()
{
    extern __shared__ char smem_raw[];
    FlashSmem& sm = *reinterpret_cast<FlashSmem*>(smem_raw);

    const int tid = threadIdx.x;
    const int qt  = blockIdx.x;          // q tile: 0..31
    const int bh  = blockIdx.y;          // 0..31
    const int b   = bh / NH;
    const int h   = bh % NH;

    const size_t rowbase = (size_t)b * SEQ;
    const int    colbase = h * HDIM;

    // ---- load Q tile (transposed into smem) ----
    #pragma unroll
    for (int i = 0; i < 8; i++) {
        const int f = tid + i * 256;       // 0..2047
        const int r = f >> 5;              // 0..63
        const int c = (f & 31) << 2;       // 0..124
        float4 v = *(const float4*)(g_q + (rowbase + qt * FBQ + r) * DIMV + colbase + c);
        sm.Qt[c + 0][r] = v.x;
        sm.Qt[c + 1][r] = v.y;
        sm.Qt[c + 2][r] = v.z;
        sm.Qt[c + 3][r] = v.w;
    }
    if (tid < FBQ) { sm.m_s[tid] = -1e30f; sm.l_s[tid] = 0.0f; }

    // output accumulators: rows ry*4.., cols cx*8..
    const int ry = tid >> 4;   // 0..15 (4 rows each)
    const int cx = tid & 15;   // 0..15 (8 cols each)
    float o[4][8] = {};

    for (int j = 0; j <= qt; j++) {
        __syncthreads();   // Q/stats ready (j=0); Kt/Vs/Ss free from prev iter

        // ---- load K (transposed) and V tiles ----
        #pragma unroll
        for (int i = 0; i < 8; i++) {
            const int f = tid + i * 256;
            const int r = f >> 5;
            const int c = (f & 31) << 2;
            const size_t goff = (rowbase + j * FBK + r) * DIMV + colbase + c;
            float4 kv = *(const float4*)(g_k + goff);
            sm.Kt[c + 0][r] = kv.x;
            sm.Kt[c + 1][r] = kv.y;
            sm.Kt[c + 2][r] = kv.z;
            sm.Kt[c + 3][r] = kv.w;
            *(float4*)(&sm.Vs[r][c]) = *(const float4*)(g_v + goff);
        }
        __syncthreads();

        // ---- scores: S = Q @ K^T (4x4 per thread) ----
        float sacc[4][4] = {};
        #pragma unroll 4
        for (int kk = 0; kk < HDIM; kk++) {
            float qv[4], kv[4];
            #pragma unroll
            for (int i = 0; i < 4; i++) qv[i] = sm.Qt[kk][ry * 4 + i];
            #pragma unroll
            for (int jj = 0; jj < 4; jj++) kv[jj] = sm.Kt[kk][cx * 4 + jj];
            #pragma unroll
            for (int i = 0; i < 4; i++)
                #pragma unroll
                for (int jj = 0; jj < 4; jj++)
                    sacc[i][jj] = fmaf(qv[i], kv[jj], sacc[i][jj]);
        }
        const bool diag = (j == qt);
        #pragma unroll
        for (int i = 0; i < 4; i++) {
            const int qrow = qt * FBQ + ry * 4 + i;
            #pragma unroll
            for (int jj = 0; jj < 4; jj++) {
                const int kcol = j * FBK + cx * 4 + jj;
                float sv = sacc[i][jj];
                if (diag && kcol > qrow) sv = -1e30f;
                sm.Ss[ry * 4 + i][cx * 4 + jj] = sv;
            }
        }
        __syncthreads();

        // ---- online softmax row update (64 threads, 1 row each) ----
        if (tid < FBQ) {
            const int r = tid;
            float mold = sm.m_s[r];
            float mnew = mold;
            #pragma unroll 8
            for (int c = 0; c < FBK; c++) mnew = fmaxf(mnew, sm.Ss[r][c]);
            const float f = __expf(mold - mnew);
            float sum = 0.0f;
            #pragma unroll 4
            for (int c = 0; c < FBK; c++) {
                float p = __expf(sm.Ss[r][c] - mnew);
                sm.Ss[r][c] = p;
                sum += p;
            }
            sm.m_s[r]  = mnew;
            sm.l_s[r]  = sm.l_s[r] * f + sum;
            sm.sc_s[r] = f;
        }
        __syncthreads();

        // ---- rescale O, accumulate P @ V ----
        float fsc[4];
        #pragma unroll
        for (int i = 0; i < 4; i++) fsc[i] = sm.sc_s[ry * 4 + i];
        #pragma unroll
        for (int i = 0; i < 4; i++)
            #pragma unroll
            for (int k = 0; k < 8; k++) o[i][k] *= fsc[i];

        #pragma unroll 2
        for (int c = 0; c < FBK; c++) {
            float p[4];
            #pragma unroll
            for (int i = 0; i < 4; i++) p[i] = sm.Ss[ry * 4 + i][c];
            float4 v0 = *(const float4*)(&sm.Vs[c][cx * 8]);
            float4 v1 = *(const float4*)(&sm.Vs[c][cx * 8 + 4]);
            #pragma unroll
            for (int i = 0; i < 4; i++) {
                o[i][0] = fmaf(p[i], v0.x, o[i][0]);
                o[i][1] = fmaf(p[i], v0.y, o[i][1]);
                o[i][2] = fmaf(p[i], v0.z, o[i][2]);
                o[i][3] = fmaf(p[i], v0.w, o[i][3]);
                o[i][4] = fmaf(p[i], v1.x, o[i][4]);
                o[i][5] = fmaf(p[i], v1.y, o[i][5]);
                o[i][6] = fmaf(p[i], v1.z, o[i][6]);
                o[i][7] = fmaf(p[i], v1.w, o[i][7]);
            }
        }
    }

    // ---- epilogue: divide by l, write to g_ao in (b,s,dim) layout ----
    #pragma unroll
    for (int i = 0; i < 4; i++) {
        const int r = ry * 4 + i;
        const float inv = 1.0f / sm.l_s[r];
        const size_t off = (rowbase + qt * FBQ + r) * DIMV + colbase + cx * 8;
        *(float4*)(g_ao + off) =
            make_float4(o[i][0] * inv, o[i][1] * inv, o[i][2] * inv, o[i][3] * inv);
        *(float4*)(g_ao + off + 4) =
            make_float4(o[i][4] * inv, o[i][5] * inv, o[i][6] * inv, o[i][7] * inv);
    }
}

// ---------------------------------------------------------------------------
extern "C" void kernel_launch(void* const* d_in, const int* in_sizes, int n_in,
                              void* d_out, int out_size)
{
    const float* x  = (const float*)d_in[0];
    const float* fc = (const float*)d_in[1];
    const float* fs = (const float*)d_in[2];
    // d_in[3] = mask (unused: causal mask applied analytically)
    const float* wq = (const float*)d_in[4];
    const float* wk = (const float*)d_in[5];
    const float* wv = (const float*)d_in[6];
    const float* wo = (const float*)d_in[7];
    float* out = (float*)d_out;

    cudaFuncSetAttribute(flash_kernel,
                         cudaFuncAttributeMaxDynamicSharedMemorySize,
                         (int)sizeof(FlashSmem));

    // 1) QKV projections
    dim3 gq(DIMV / GBN, MROWS / GBM, 3);
    qkv_kernel<<<gq, 256>>>(x, wq, wk, wv);

    // 2) RoPE (+ q scaling)
    const int npairs = BATCH * SEQ * NH * (HDIM / 2);   // 2^22
    rope_kernel<<<npairs / 256, 256>>>(fc, fs);

    // 3) Causal flash attention
    flash_kernel<<<dim3(SEQ / FBQ, BATCH * NH), 256, sizeof(FlashSmem)>>>();

    // 4) Output projection
    oproj_kernel<<<dim3(DIMV / GBN, MROWS / GBM), 256>>>(wo, out);
}

// round 6
// speedup vs baseline: 1.4134x; 1.4134x over previous
#include <cuda_runtime.h>
#include <cuda_bf16.h>
#include <mma.h>
#include <cstdint>
#include <math.h>

using namespace nvcuda;

// Problem constants
constexpr int BATCH = 2;
constexpr int SEQ   = 2048;
constexpr int DIMV  = 2048;
constexpr int NH    = 16;
constexpr int HDIM  = 128;
constexpr int MROWS = BATCH * SEQ;  // 4096
constexpr float QSCALE = 0.08838834764831845f;  // 1/sqrt(128)

// ---------------------------------------------------------------------------
// Device-global scratch (no runtime allocation allowed).
// NOTE: device globals must NEVER be passed as kernel arguments from host
// code — on GB300 ATS silently turns the host shadow address into a valid
// host-memory pointer (R3-R5 bug). Reference them inside kernels only.
// ---------------------------------------------------------------------------
__device__ float g_q [MROWS * DIMV];
__device__ float g_k [MROWS * DIMV];
__device__ float g_v [MROWS * DIMV];
__device__ float g_ao[MROWS * DIMV];

// Transposed split weights: [N=2048][K=2048] K-major, value = W[k][n]
__device__ __nv_bfloat16 g_wqh[DIMV * DIMV];
__device__ __nv_bfloat16 g_wqm[DIMV * DIMV];
__device__ __nv_bfloat16 g_wkh[DIMV * DIMV];
__device__ __nv_bfloat16 g_wkm[DIMV * DIMV];
__device__ __nv_bfloat16 g_wvh[DIMV * DIMV];
__device__ __nv_bfloat16 g_wvm[DIMV * DIMV];
__device__ __nv_bfloat16 g_woh[DIMV * DIMV];
__device__ __nv_bfloat16 g_wom[DIMV * DIMV];

// ---------------------------------------------------------------------------
// Weight transpose + split: w [K,N] fp32 -> whT, wmT [N,K] bf16.
// Output symbols selected by blockIdx.z INSIDE device code.
// ---------------------------------------------------------------------------
__global__ void split_wT_kernel(const float* __restrict__ wq,
                                const float* __restrict__ wk,
                                const float* __restrict__ wv,
                                const float* __restrict__ wo)
{
    const int z = blockIdx.z;
    const float* w = (z == 0) ? wq : (z == 1) ? wk : (z == 2) ? wv : wo;
    __nv_bfloat16* whT = (z == 0) ? g_wqh : (z == 1) ? g_wkh
                        : (z == 2) ? g_wvh : g_woh;
    __nv_bfloat16* wmT = (z == 0) ? g_wqm : (z == 1) ? g_wkm
                        : (z == 2) ? g_wvm : g_wom;

    __shared__ float t[32][33];
    const int n0 = blockIdx.x * 32;
    const int k0 = blockIdx.y * 32;
    const int tx = threadIdx.x;        // 0..31
    const int ty = threadIdx.y;        // 0..7
    #pragma unroll
    for (int i = ty; i < 32; i += 8)
        t[i][tx] = w[(size_t)(k0 + i) * DIMV + n0 + tx];
    __syncthreads();
    #pragma unroll
    for (int i = ty; i < 32; i += 8) {
        float a = t[tx][i];    // = w[k0+tx][n0+i]
        __nv_bfloat16 bh = __float2bfloat16_rn(a);
        __nv_bfloat16 bm = __float2bfloat16_rn(a - __bfloat162float(bh));
        whT[(size_t)(n0 + i) * DIMV + k0 + tx] = bh;
        wmT[(size_t)(n0 + i) * DIMV + k0 + tx] = bm;
    }
}

// ---------------------------------------------------------------------------
// WMMA bf16 split GEMM: C[M,N] = A[M,K] @ W[K,N]
// A fp32 (hi/mid split in-kernel), W pre-split+transposed bf16 [N][K].
// D = Ah*Bh + Am*Bh + Ah*Bm, fp32 accumulate.
// CTA tile 128x128, BK=16, 8 warps (4m x 2n), warp tile 32x64.
// Static smem (48KB exactly), double buffered, register-prefetched loads.
// ---------------------------------------------------------------------------
constexpr int BM = 128, BN = 128, BK = 16;
constexpr int LDT = 24;                 // smem row stride in halves (48 B)
constexpr int NKSTEP = DIMV / BK;       // 128

__device__ __forceinline__ void split8(const float4& v0, const float4& v1,
                                       uint4& hi, uint4& mid)
{
    const float a[8] = {v0.x, v0.y, v0.z, v0.w, v1.x, v1.y, v1.z, v1.w};
    uint32_t h[4], m[4];
    #pragma unroll
    for (int i = 0; i < 4; i++) {
        __nv_bfloat16 hx = __float2bfloat16_rn(a[2 * i]);
        __nv_bfloat16 hy = __float2bfloat16_rn(a[2 * i + 1]);
        __nv_bfloat16 mx = __float2bfloat16_rn(a[2 * i]     - __bfloat162float(hx));
        __nv_bfloat16 my = __float2bfloat16_rn(a[2 * i + 1] - __bfloat162float(hy));
        h[i] = (uint32_t)__bfloat16_as_ushort(hx) |
               ((uint32_t)__bfloat16_as_ushort(hy) << 16);
        m[i] = (uint32_t)__bfloat16_as_ushort(mx) |
               ((uint32_t)__bfloat16_as_ushort(my) << 16);
    }
    hi  = make_uint4(h[0], h[1], h[2], h[3]);
    mid = make_uint4(m[0], m[1], m[2], m[3]);
}

__device__ __forceinline__ void wgemm_body(const float* __restrict__ A,
                                           const __nv_bfloat16* __restrict__ BhT,
                                           const __nv_bfloat16* __restrict__ BmT,
                                           float* __restrict__ C)
{
    // smem: [stage][mat][128*24] halves; mats: 0=Ah 1=Am 2=Bh 3=Bm
    __shared__ __nv_bfloat16 tiles[2][4][BM * LDT];   // 49152 bytes

    constexpr int K = DIMV, N = DIMV;
    const int tid  = threadIdx.x;
    const int wid  = tid >> 5;
    const int wm   = wid & 3;        // 4 m-warps (rows wm*32)
    const int wn   = wid >> 2;       // 2 n-warps (cols wn*64)
    const int brow = blockIdx.y * BM;
    const int bcol = blockIdx.x * BN;

    // load assignment: row = tid>>1 (0..127), half = tid&1 -> k offset 0 or 8
    const int lrow = tid >> 1;
    const int lk   = (tid & 1) * 8;

    float4 pa0, pa1;     // 8 fp32 of A
    uint4  pbh, pbm;     // 8 bf16 of Bh / Bm

    auto prefetch = [&](int kt) {
        const int k0 = kt * BK + lk;
        const float* ap = A + (size_t)(brow + lrow) * K + k0;
        pa0 = *(const float4*)(ap);
        pa1 = *(const float4*)(ap + 4);
        pbh = *(const uint4*)(BhT + (size_t)(bcol + lrow) * K + k0);
        pbm = *(const uint4*)(BmT + (size_t)(bcol + lrow) * K + k0);
    };

    wmma::fragment<wmma::accumulator, 16, 16, 16, float> facc[2][4];
    #pragma unroll
    for (int mt = 0; mt < 2; mt++)
        #pragma unroll
        for (int nt = 0; nt < 4; nt++)
            wmma::fill_fragment(facc[mt][nt], 0.0f);

    prefetch(0);

    #pragma unroll 1
    for (int kt = 0; kt < NKSTEP; kt++) {
        const int st = kt & 1;

        // ---- stage into smem (A split hi/mid in regs) ----
        {
            uint4 ah, am;
            split8(pa0, pa1, ah, am);
            const int off = lrow * LDT + lk;      // halves
            *(uint4*)(&tiles[st][0][off]) = ah;
            *(uint4*)(&tiles[st][1][off]) = am;
            *(uint4*)(&tiles[st][2][off]) = pbh;
            *(uint4*)(&tiles[st][3][off]) = pbm;
        }
        __syncthreads();

        if (kt + 1 < NKSTEP) prefetch(kt + 1);

        // ---- compute ----
        wmma::fragment<wmma::matrix_a, 16, 16, 16, __nv_bfloat16, wmma::row_major> fah[2], fam[2];
        wmma::fragment<wmma::matrix_b, 16, 16, 16, __nv_bfloat16, wmma::col_major> fb[4];

        #pragma unroll
        for (int mt = 0; mt < 2; mt++) {
            wmma::load_matrix_sync(fah[mt], &tiles[st][0][(wm * 32 + mt * 16) * LDT], LDT);
            wmma::load_matrix_sync(fam[mt], &tiles[st][1][(wm * 32 + mt * 16) * LDT], LDT);
        }
        #pragma unroll
        for (int nt = 0; nt < 4; nt++)
            wmma::load_matrix_sync(fb[nt], &tiles[st][2][(wn * 64 + nt * 16) * LDT], LDT);

        #pragma unroll
        for (int mt = 0; mt < 2; mt++)
            #pragma unroll
            for (int nt = 0; nt < 4; nt++)
                wmma::mma_sync(facc[mt][nt], fah[mt], fb[nt], facc[mt][nt]);
        #pragma unroll
        for (int mt = 0; mt < 2; mt++)
            #pragma unroll
            for (int nt = 0; nt < 4; nt++)
                wmma::mma_sync(facc[mt][nt], fam[mt], fb[nt], facc[mt][nt]);

        #pragma unroll
        for (int nt = 0; nt < 4; nt++)
            wmma::load_matrix_sync(fb[nt], &tiles[st][3][(wn * 64 + nt * 16) * LDT], LDT);
        #pragma unroll
        for (int mt = 0; mt < 2; mt++)
            #pragma unroll
            for (int nt = 0; nt < 4; nt++)
                wmma::mma_sync(facc[mt][nt], fah[mt], fb[nt], facc[mt][nt]);
        // safe without trailing sync: next write to stage st happens only
        // after the __syncthreads() of iteration kt+1 (hazard-audited)
    }

    // ---- epilogue ----
    #pragma unroll
    for (int mt = 0; mt < 2; mt++)
        #pragma unroll
        for (int nt = 0; nt < 4; nt++) {
            float* cp = C + (size_t)(brow + wm * 32 + mt * 16) * N
                          + bcol + wn * 64 + nt * 16;
            wmma::store_matrix_sync(cp, facc[mt][nt], N, wmma::mem_row_major);
        }
}

__global__ __launch_bounds__(256) void qkv_mma_kernel(const float* __restrict__ x)
{
    const __nv_bfloat16* bh = (blockIdx.z == 0) ? g_wqh : (blockIdx.z == 1) ? g_wkh : g_wvh;
    const __nv_bfloat16* bm = (blockIdx.z == 0) ? g_wqm : (blockIdx.z == 1) ? g_wkm : g_wvm;
    float* out              = (blockIdx.z == 0) ? g_q   : (blockIdx.z == 1) ? g_k   : g_v;
    wgemm_body(x, bh, bm, out);
}

__global__ __launch_bounds__(256) void oproj_mma_kernel(float* __restrict__ out)
{
    wgemm_body(g_ao, g_woh, g_wom, out);
}

// ---------------------------------------------------------------------------
// RoPE on Q (with q-scale folded in) and K, in place.
// ---------------------------------------------------------------------------
__global__ __launch_bounds__(256) void rope_kernel(const float* __restrict__ cs,
                                                   const float* __restrict__ sn)
{
    const int p = blockIdx.x * blockDim.x + threadIdx.x;
    const int d = p & 63;
    const int h = (p >> 6) & (NH - 1);
    const int s = (p >> 10) & (SEQ - 1);
    const int b = p >> 21;

    const float c  = cs[s * 64 + d];
    const float si = sn[s * 64 + d];

    const size_t off = (size_t)(b * SEQ + s) * DIMV + h * HDIM + 2 * d;

    float qr = g_q[off], qi = g_q[off + 1];
    g_q[off]     = (qr * c - qi * si) * QSCALE;
    g_q[off + 1] = (qr * si + qi * c) * QSCALE;

    float kr = g_k[off], ki = g_k[off + 1];
    g_k[off]     = kr * c - ki * si;
    g_k[off + 1] = kr * si + ki * c;
}

// ---------------------------------------------------------------------------
// Flash-style causal attention, fp32 (R1-proven, unchanged).
// ---------------------------------------------------------------------------
constexpr int FBQ = 64;
constexpr int FBK = 64;

struct FlashSmem {
    float Qt[HDIM][FBQ + 4];
    float Kt[HDIM][FBK + 4];
    float Vs[FBK][HDIM];
    float Ss[FBQ][FBK + 4];
    float m_s[FBQ];
    float l_s[FBQ];
    float sc_s[FBQ];
};

__global__ __launch_bounds__(256) void flash_kernel()
{
    extern __shared__ char smem_raw[];
    FlashSmem& sm = *reinterpret_cast<FlashSmem*>(smem_raw);

    const int tid = threadIdx.x;
    const int qt  = blockIdx.x;
    const int bh  = blockIdx.y;
    const int b   = bh / NH;
    const int h   = bh % NH;

    const size_t rowbase = (size_t)b * SEQ;
    const int    colbase = h * HDIM;

    #pragma unroll
    for (int i = 0; i < 8; i++) {
        const int f = tid + i * 256;
        const int r = f >> 5;
        const int c = (f & 31) << 2;
        float4 v = *(const float4*)(g_q + (rowbase + qt * FBQ + r) * DIMV + colbase + c);
        sm.Qt[c + 0][r] = v.x;
        sm.Qt[c + 1][r] = v.y;
        sm.Qt[c + 2][r] = v.z;
        sm.Qt[c + 3][r] = v.w;
    }
    if (tid < FBQ) { sm.m_s[tid] = -1e30f; sm.l_s[tid] = 0.0f; }

    const int ry = tid >> 4;
    const int cx = tid & 15;
    float o[4][8] = {};

    for (int j = 0; j <= qt; j++) {
        __syncthreads();

        #pragma unroll
        for (int i = 0; i < 8; i++) {
            const int f = tid + i * 256;
            const int r = f >> 5;
            const int c = (f & 31) << 2;
            const size_t goff = (rowbase + j * FBK + r) * DIMV + colbase + c;
            float4 kv = *(const float4*)(g_k + goff);
            sm.Kt[c + 0][r] = kv.x;
            sm.Kt[c + 1][r] = kv.y;
            sm.Kt[c + 2][r] = kv.z;
            sm.Kt[c + 3][r] = kv.w;
            *(float4*)(&sm.Vs[r][c]) = *(const float4*)(g_v + goff);
        }
        __syncthreads();

        float sacc[4][4] = {};
        #pragma unroll 4
        for (int kk = 0; kk < HDIM; kk++) {
            float qv[4], kv[4];
            #pragma unroll
            for (int i = 0; i < 4; i++) qv[i] = sm.Qt[kk][ry * 4 + i];
            #pragma unroll
            for (int jj = 0; jj < 4; jj++) kv[jj] = sm.Kt[kk][cx * 4 + jj];
            #pragma unroll
            for (int i = 0; i < 4; i++)
                #pragma unroll
                for (int jj = 0; jj < 4; jj++)
                    sacc[i][jj] = fmaf(qv[i], kv[jj], sacc[i][jj]);
        }
        const bool diag = (j == qt);
        #pragma unroll
        for (int i = 0; i < 4; i++) {
            const int qrow = qt * FBQ + ry * 4 + i;
            #pragma unroll
            for (int jj = 0; jj < 4; jj++) {
                const int kcol = j * FBK + cx * 4 + jj;
                float sv = sacc[i][jj];
                if (diag && kcol > qrow) sv = -1e30f;
                sm.Ss[ry * 4 + i][cx * 4 + jj] = sv;
            }
        }
        __syncthreads();

        if (tid < FBQ) {
            const int r = tid;
            float mold = sm.m_s[r];
            float mnew = mold;
            #pragma unroll 8
            for (int c = 0; c < FBK; c++) mnew = fmaxf(mnew, sm.Ss[r][c]);
            const float f = __expf(mold - mnew);
            float sum = 0.0f;
            #pragma unroll 4
            for (int c = 0; c < FBK; c++) {
                float p = __expf(sm.Ss[r][c] - mnew);
                sm.Ss[r][c] = p;
                sum += p;
            }
            sm.m_s[r]  = mnew;
            sm.l_s[r]  = sm.l_s[r] * f + sum;
            sm.sc_s[r] = f;
        }
        __syncthreads();

        float fsc[4];
        #pragma unroll
        for (int i = 0; i < 4; i++) fsc[i] = sm.sc_s[ry * 4 + i];
        #pragma unroll
        for (int i = 0; i < 4; i++)
            #pragma unroll
            for (int k = 0; k < 8; k++) o[i][k] *= fsc[i];

        #pragma unroll 2
        for (int c = 0; c < FBK; c++) {
            float p[4];
            #pragma unroll
            for (int i = 0; i < 4; i++) p[i] = sm.Ss[ry * 4 + i][c];
            float4 v0 = *(const float4*)(&sm.Vs[c][cx * 8]);
            float4 v1 = *(const float4*)(&sm.Vs[c][cx * 8 + 4]);
            #pragma unroll
            for (int i = 0; i < 4; i++) {
                o[i][0] = fmaf(p[i], v0.x, o[i][0]);
                o[i][1] = fmaf(p[i], v0.y, o[i][1]);
                o[i][2] = fmaf(p[i], v0.z, o[i][2]);
                o[i][3] = fmaf(p[i], v0.w, o[i][3]);
                o[i][4] = fmaf(p[i], v1.x, o[i][4]);
                o[i][5] = fmaf(p[i], v1.y, o[i][5]);
                o[i][6] = fmaf(p[i], v1.z, o[i][6]);
                o[i][7] = fmaf(p[i], v1.w, o[i][7]);
            }
        }
    }

    #pragma unroll
    for (int i = 0; i < 4; i++) {
        const int r = ry * 4 + i;
        const float inv = 1.0f / sm.l_s[r];
        const size_t off = (rowbase + qt * FBQ + r) * DIMV + colbase + cx * 8;
        *(float4*)(g_ao + off) =
            make_float4(o[i][0] * inv, o[i][1] * inv, o[i][2] * inv, o[i][3] * inv);
        *(float4*)(g_ao + off + 4) =
            make_float4(o[i][4] * inv, o[i][5] * inv, o[i][6] * inv, o[i][7] * inv);
    }
}

// ---------------------------------------------------------------------------
extern "C" void kernel_launch(void* const* d_in, const int* in_sizes, int n_in,
                              void* d_out, int out_size)
{
    const float* x  = (const float*)d_in[0];
    const float* fc = (const float*)d_in[1];
    const float* fs = (const float*)d_in[2];
    // d_in[3] = mask (causal applied analytically)
    const float* wq = (const float*)d_in[4];
    const float* wk = (const float*)d_in[5];
    const float* wv = (const float*)d_in[6];
    const float* wo = (const float*)d_in[7];
    float* out = (float*)d_out;

    cudaFuncSetAttribute(flash_kernel,
                         cudaFuncAttributeMaxDynamicSharedMemorySize,
                         (int)sizeof(FlashSmem));

    // 1) transpose + split all four weights (outputs selected in-device)
    dim3 wtg(DIMV / 32, DIMV / 32, 4);
    dim3 wtb(32, 8);
    split_wT_kernel<<<wtg, wtb>>>(wq, wk, wv, wo);

    // 2) QKV projections (WMMA, static smem)
    qkv_mma_kernel<<<dim3(DIMV / BN, MROWS / BM, 3), 256>>>(x);

    // 3) RoPE (+ q scaling)
    const int npairs = BATCH * SEQ * NH * (HDIM / 2);
    rope_kernel<<<npairs / 256, 256>>>(fc, fs);

    // 4) Causal flash attention (fp32)
    flash_kernel<<<dim3(SEQ / FBQ, BATCH * NH), 256, sizeof(FlashSmem)>>>();

    // 5) output projection (WMMA, static smem)
    oproj_mma_kernel<<<dim3(DIMV / BN, MROWS / BM), 256>>>(out);
}

// round 7
// speedup vs baseline: 1.4887x; 1.0533x over previous
#include <cuda_runtime.h>
#include <cuda_bf16.h>
#include <cstdint>
#include <math.h>

// Problem constants
constexpr int BATCH = 2;
constexpr int SEQ   = 2048;
constexpr int DIMV  = 2048;
constexpr int NH    = 16;
constexpr int HDIM  = 128;
constexpr int MROWS = BATCH * SEQ;  // 4096
constexpr float QSCALE = 0.08838834764831845f;  // 1/sqrt(128)

// ---------------------------------------------------------------------------
// Device-global scratch. RULE (R3-R5 bug): device globals must NEVER be passed
// as kernel arguments from host code — GB300 ATS silently accepts the host
// shadow address. Reference them inside kernels only.
// ---------------------------------------------------------------------------
__device__ float g_q [MROWS * DIMV];
__device__ float g_k [MROWS * DIMV];
__device__ float g_v [MROWS * DIMV];
__device__ float g_ao[MROWS * DIMV];

// Transposed split weights: [N=2048][K=2048] K-major, value = W[k][n]
__device__ __nv_bfloat16 g_wqh[DIMV * DIMV];
__device__ __nv_bfloat16 g_wqm[DIMV * DIMV];
__device__ __nv_bfloat16 g_wkh[DIMV * DIMV];
__device__ __nv_bfloat16 g_wkm[DIMV * DIMV];
__device__ __nv_bfloat16 g_wvh[DIMV * DIMV];
__device__ __nv_bfloat16 g_wvm[DIMV * DIMV];
__device__ __nv_bfloat16 g_woh[DIMV * DIMV];
__device__ __nv_bfloat16 g_wom[DIMV * DIMV];

// ---------------------------------------------------------------------------
// helpers
// ---------------------------------------------------------------------------
__device__ __forceinline__ uint32_t smem_u32(const void* p) {
    uint32_t a;
    asm("{ .reg .u64 t; cvta.to.shared.u64 t, %1; cvt.u32.u64 %0, t; }"
        : "=r"(a) : "l"(p));
    return a;
}

__device__ __forceinline__ void mma16816(float d[4], const uint32_t a[4],
                                         const uint32_t b0, const uint32_t b1) {
    asm volatile(
        "mma.sync.aligned.m16n8k16.row.col.f32.bf16.bf16.f32 "
        "{%0,%1,%2,%3}, {%4,%5,%6,%7}, {%8,%9}, {%0,%1,%2,%3};"
        : "+f"(d[0]), "+f"(d[1]), "+f"(d[2]), "+f"(d[3])
        : "r"(a[0]), "r"(a[1]), "r"(a[2]), "r"(a[3]), "r"(b0), "r"(b1));
}

#define LDSM_X4(r0, r1, r2, r3, addr)                                  \
    asm volatile("ldmatrix.sync.aligned.m8n8.x4.shared.b16 "           \
                 "{%0,%1,%2,%3}, [%4];"                                \
                 : "=r"(r0), "=r"(r1), "=r"(r2), "=r"(r3) : "r"(addr))

__device__ __forceinline__ void split8(const float4& v0, const float4& v1,
                                       uint4& hi, uint4& mid)
{
    const float a[8] = {v0.x, v0.y, v0.z, v0.w, v1.x, v1.y, v1.z, v1.w};
    uint32_t h[4], m[4];
    #pragma unroll
    for (int i = 0; i < 4; i++) {
        __nv_bfloat16 hx = __float2bfloat16_rn(a[2 * i]);
        __nv_bfloat16 hy = __float2bfloat16_rn(a[2 * i + 1]);
        __nv_bfloat16 mx = __float2bfloat16_rn(a[2 * i]     - __bfloat162float(hx));
        __nv_bfloat16 my = __float2bfloat16_rn(a[2 * i + 1] - __bfloat162float(hy));
        h[i] = (uint32_t)__bfloat16_as_ushort(hx) |
               ((uint32_t)__bfloat16_as_ushort(hy) << 16);
        m[i] = (uint32_t)__bfloat16_as_ushort(mx) |
               ((uint32_t)__bfloat16_as_ushort(my) << 16);
    }
    hi  = make_uint4(h[0], h[1], h[2], h[3]);
    mid = make_uint4(m[0], m[1], m[2], m[3]);
}

// ---------------------------------------------------------------------------
// Weight transpose + split: w [K,N] fp32 -> whT, wmT [N,K] bf16.
// Output symbols selected by blockIdx.z INSIDE device code.
// ---------------------------------------------------------------------------
__global__ void split_wT_kernel(const float* __restrict__ wq,
                                const float* __restrict__ wk,
                                const float* __restrict__ wv,
                                const float* __restrict__ wo)
{
    const int z = blockIdx.z;
    const float* w = (z == 0) ? wq : (z == 1) ? wk : (z == 2) ? wv : wo;
    __nv_bfloat16* whT = (z == 0) ? g_wqh : (z == 1) ? g_wkh
                        : (z == 2) ? g_wvh : g_woh;
    __nv_bfloat16* wmT = (z == 0) ? g_wqm : (z == 1) ? g_wkm
                        : (z == 2) ? g_wvm : g_wom;

    __shared__ float t[32][33];
    const int n0 = blockIdx.x * 32;
    const int k0 = blockIdx.y * 32;
    const int tx = threadIdx.x;        // 0..31
    const int ty = threadIdx.y;        // 0..7
    #pragma unroll
    for (int i = ty; i < 32; i += 8)
        t[i][tx] = w[(size_t)(k0 + i) * DIMV + n0 + tx];
    __syncthreads();
    #pragma unroll
    for (int i = ty; i < 32; i += 8) {
        float a = t[tx][i];    // = w[k0+tx][n0+i]
        __nv_bfloat16 bh = __float2bfloat16_rn(a);
        __nv_bfloat16 bm = __float2bfloat16_rn(a - __bfloat162float(bh));
        whT[(size_t)(n0 + i) * DIMV + k0 + tx] = bh;
        wmT[(size_t)(n0 + i) * DIMV + k0 + tx] = bm;
    }
}

// ---------------------------------------------------------------------------
// mma.sync bf16 split GEMM: C[M,N] = A[M,K] @ W[K,N]
// A fp32 (hi/mid split in-kernel), W pre-split+transposed bf16 [N][K].
// D = Ah*Bh + Ah*Bm + Am*Bh, fp32 accumulate.
// CTA 128x128, BK=32, 8 warps (2m x 4n), warp tile 64x32, ldmatrix fragments.
// ---------------------------------------------------------------------------
constexpr int BM = 128, BN = 128, BK = 32;
constexpr int RSTRB  = 80;                 // smem row stride bytes (64 data + pad)
constexpr int TILE_B = 128 * RSTRB;        // 10240
constexpr int STG_B  = 4 * TILE_B;         // Ah,Am,Bh,Bm = 40960
constexpr int GSMEM  = 2 * STG_B;          // 81920
constexpr int NKSTEP = DIMV / BK;          // 64

__device__ __forceinline__ void hgemm_body(const float* __restrict__ A,
                                           const __nv_bfloat16* __restrict__ BhT,
                                           const __nv_bfloat16* __restrict__ BmT,
                                           float* __restrict__ C)
{
    extern __shared__ char smem[];
    constexpr int K = DIMV, N = DIMV;

    const int tid  = threadIdx.x;
    const int wid  = tid >> 5;
    const int lane = tid & 31;
    const int gid  = lane >> 2;
    const int tq   = lane & 3;
    const int wm   = wid & 1;        // 2 m-warps -> rows wm*64
    const int wn   = wid >> 1;       // 4 n-warps -> cols wn*32

    const int brow = blockIdx.y * BM;
    const int bcol = blockIdx.x * BN;

    const uint32_t sb = smem_u32(smem);

    // ldmatrix lane address components
    const int la = lane & 7;
    const int lb = (lane >> 3) & 1;
    const int lc = lane >> 4;
    // A x4: lanes 0-7 rows0-7/k0, 8-15 rows8-15/k0, 16-23 rows0-7/k16B, 24-31 rows8-15/k16B
    const uint32_t a_off = (uint32_t)(la + lb * 8) * RSTRB + lc * 16;
    // B x4 (two n8 tiles): lanes 0-7 n0-7/k0, 8-15 n0-7/k16B, 16-23 n8-15/k0, 24-31 n8-15/k16B
    const uint32_t b_off = (uint32_t)(la + lc * 8) * RSTRB + lb * 16;

    // staging assignment: row = tid>>1 (0..127), half = (tid&1)*16 elements
    const int lrow = tid >> 1;
    const int lke  = (tid & 1) * 16;       // element offset in k
    const uint32_t soff = (uint32_t)lrow * RSTRB + lke * 2;   // byte offset

    float4 pa[4];
    uint4  pbh[2], pbm[2];

    auto prefetch = [&](int kt) {
        const int k0 = kt * BK + lke;
        const float* ap = A + (size_t)(brow + lrow) * K + k0;
        pa[0] = *(const float4*)(ap);
        pa[1] = *(const float4*)(ap + 4);
        pa[2] = *(const float4*)(ap + 8);
        pa[3] = *(const float4*)(ap + 12);
        const __nv_bfloat16* bp = BhT + (size_t)(bcol + lrow) * K + k0;
        pbh[0] = *(const uint4*)(bp);
        pbh[1] = *(const uint4*)(bp + 8);
        const __nv_bfloat16* mp = BmT + (size_t)(bcol + lrow) * K + k0;
        pbm[0] = *(const uint4*)(mp);
        pbm[1] = *(const uint4*)(mp + 8);
    };

    float acc[4][4][4];
    #pragma unroll
    for (int mt = 0; mt < 4; mt++)
        #pragma unroll
        for (int nt = 0; nt < 4; nt++)
            #pragma unroll
            for (int r = 0; r < 4; r++) acc[mt][nt][r] = 0.0f;

    prefetch(0);

    #pragma unroll 1
    for (int kt = 0; kt < NKSTEP; kt++) {
        const int st = kt & 1;
        const uint32_t sAh = sb + st * STG_B;
        const uint32_t sAm = sAh + TILE_B;
        const uint32_t sBh = sAh + 2 * TILE_B;
        const uint32_t sBm = sAh + 3 * TILE_B;

        // ---- stage into smem ----
        {
            uint4 ah0, am0, ah1, am1;
            split8(pa[0], pa[1], ah0, am0);
            split8(pa[2], pa[3], ah1, am1);
            char* p;
            p = smem + (st * STG_B + 0 * TILE_B) + soff;
            *(uint4*)(p) = ah0;  *(uint4*)(p + 16) = ah1;
            p = smem + (st * STG_B + 1 * TILE_B) + soff;
            *(uint4*)(p) = am0;  *(uint4*)(p + 16) = am1;
            p = smem + (st * STG_B + 2 * TILE_B) + soff;
            *(uint4*)(p) = pbh[0]; *(uint4*)(p + 16) = pbh[1];
            p = smem + (st * STG_B + 3 * TILE_B) + soff;
            *(uint4*)(p) = pbm[0]; *(uint4*)(p + 16) = pbm[1];
        }
        __syncthreads();

        if (kt + 1 < NKSTEP) prefetch(kt + 1);

        // ---- compute: 2 k16 sub-steps ----
        #pragma unroll
        for (int ksub = 0; ksub < 2; ksub++) {
            const uint32_t kb = ksub * 32;   // byte offset of k16 group

            uint32_t a[4][4], bh[4][2], bm[4][2];

            #pragma unroll
            for (int mt = 0; mt < 4; mt++)
                LDSM_X4(a[mt][0], a[mt][1], a[mt][2], a[mt][3],
                        sAh + (uint32_t)(wm * 64 + mt * 16) * RSTRB + a_off + kb);
            #pragma unroll
            for (int bp = 0; bp < 2; bp++)
                LDSM_X4(bh[2 * bp][0], bh[2 * bp][1], bh[2 * bp + 1][0], bh[2 * bp + 1][1],
                        sBh + (uint32_t)(wn * 32 + bp * 16) * RSTRB + b_off + kb);

            #pragma unroll
            for (int mt = 0; mt < 4; mt++)
                #pragma unroll
                for (int nt = 0; nt < 4; nt++)
                    mma16816(acc[mt][nt], a[mt], bh[nt][0], bh[nt][1]);

            #pragma unroll
            for (int bp = 0; bp < 2; bp++)
                LDSM_X4(bm[2 * bp][0], bm[2 * bp][1], bm[2 * bp + 1][0], bm[2 * bp + 1][1],
                        sBm + (uint32_t)(wn * 32 + bp * 16) * RSTRB + b_off + kb);
            #pragma unroll
            for (int mt = 0; mt < 4; mt++)
                #pragma unroll
                for (int nt = 0; nt < 4; nt++)
                    mma16816(acc[mt][nt], a[mt], bm[nt][0], bm[nt][1]);

            #pragma unroll
            for (int mt = 0; mt < 4; mt++)
                LDSM_X4(a[mt][0], a[mt][1], a[mt][2], a[mt][3],
                        sAm + (uint32_t)(wm * 64 + mt * 16) * RSTRB + a_off + kb);
            #pragma unroll
            for (int mt = 0; mt < 4; mt++)
                #pragma unroll
                for (int nt = 0; nt < 4; nt++)
                    mma16816(acc[mt][nt], a[mt], bh[nt][0], bh[nt][1]);
        }
        // one sync per iteration (hazard-audited in R4/R6 notes)
    }

    // ---- epilogue ----
    #pragma unroll
    for (int mt = 0; mt < 4; mt++) {
        const int row0 = brow + wm * 64 + mt * 16 + gid;
        #pragma unroll
        for (int nt = 0; nt < 4; nt++) {
            const int col = bcol + wn * 32 + nt * 8 + tq * 2;
            *(float2*)(C + (size_t)row0 * N + col) =
                make_float2(acc[mt][nt][0], acc[mt][nt][1]);
            *(float2*)(C + (size_t)(row0 + 8) * N + col) =
                make_float2(acc[mt][nt][2], acc[mt][nt][3]);
        }
    }
}

__global__ __launch_bounds__(256) void qkv_mma_kernel(const float* __restrict__ x)
{
    const __nv_bfloat16* bh = (blockIdx.z == 0) ? g_wqh : (blockIdx.z == 1) ? g_wkh : g_wvh;
    const __nv_bfloat16* bm = (blockIdx.z == 0) ? g_wqm : (blockIdx.z == 1) ? g_wkm : g_wvm;
    float* out              = (blockIdx.z == 0) ? g_q   : (blockIdx.z == 1) ? g_k   : g_v;
    hgemm_body(x, bh, bm, out);
}

__global__ __launch_bounds__(256) void oproj_mma_kernel(float* __restrict__ out)
{
    hgemm_body(g_ao, g_woh, g_wom, out);
}

// ---------------------------------------------------------------------------
// RoPE on Q (with q-scale folded in) and K, in place.
// ---------------------------------------------------------------------------
__global__ __launch_bounds__(256) void rope_kernel(const float* __restrict__ cs,
                                                   const float* __restrict__ sn)
{
    const int p = blockIdx.x * blockDim.x + threadIdx.x;
    const int d = p & 63;
    const int h = (p >> 6) & (NH - 1);
    const int s = (p >> 10) & (SEQ - 1);
    const int b = p >> 21;

    const float c  = cs[s * 64 + d];
    const float si = sn[s * 64 + d];

    const size_t off = (size_t)(b * SEQ + s) * DIMV + h * HDIM + 2 * d;

    float qr = g_q[off], qi = g_q[off + 1];
    g_q[off]     = (qr * c - qi * si) * QSCALE;
    g_q[off + 1] = (qr * si + qi * c) * QSCALE;

    float kr = g_k[off], ki = g_k[off + 1];
    g_k[off]     = kr * c - ki * si;
    g_k[off + 1] = kr * si + ki * c;
}

// ---------------------------------------------------------------------------
// Flash-style causal attention, fp32 (R1/R6-proven, unchanged).
// ---------------------------------------------------------------------------
constexpr int FBQ = 64;
constexpr int FBK = 64;

struct FlashSmem {
    float Qt[HDIM][FBQ + 4];
    float Kt[HDIM][FBK + 4];
    float Vs[FBK][HDIM];
    float Ss[FBQ][FBK + 4];
    float m_s[FBQ];
    float l_s[FBQ];
    float sc_s[FBQ];
};

__global__ __launch_bounds__(256) void flash_kernel()
{
    extern __shared__ char smem_raw[];
    FlashSmem& sm = *reinterpret_cast<FlashSmem*>(smem_raw);

    const int tid = threadIdx.x;
    const int qt  = blockIdx.x;
    const int bh  = blockIdx.y;
    const int b   = bh / NH;
    const int h   = bh % NH;

    const size_t rowbase = (size_t)b * SEQ;
    const int    colbase = h * HDIM;

    #pragma unroll
    for (int i = 0; i < 8; i++) {
        const int f = tid + i * 256;
        const int r = f >> 5;
        const int c = (f & 31) << 2;
        float4 v = *(const float4*)(g_q + (rowbase + qt * FBQ + r) * DIMV + colbase + c);
        sm.Qt[c + 0][r] = v.x;
        sm.Qt[c + 1][r] = v.y;
        sm.Qt[c + 2][r] = v.z;
        sm.Qt[c + 3][r] = v.w;
    }
    if (tid < FBQ) { sm.m_s[tid] = -1e30f; sm.l_s[tid] = 0.0f; }

    const int ry = tid >> 4;
    const int cx = tid & 15;
    float o[4][8] = {};

    for (int j = 0; j <= qt; j++) {
        __syncthreads();

        #pragma unroll
        for (int i = 0; i < 8; i++) {
            const int f = tid + i * 256;
            const int r = f >> 5;
            const int c = (f & 31) << 2;
            const size_t goff = (rowbase + j * FBK + r) * DIMV + colbase + c;
            float4 kv = *(const float4*)(g_k + goff);
            sm.Kt[c + 0][r] = kv.x;
            sm.Kt[c + 1][r] = kv.y;
            sm.Kt[c + 2][r] = kv.z;
            sm.Kt[c + 3][r] = kv.w;
            *(float4*)(&sm.Vs[r][c]) = *(const float4*)(g_v + goff);
        }
        __syncthreads();

        float sacc[4][4] = {};
        #pragma unroll 4
        for (int kk = 0; kk < HDIM; kk++) {
            float qv[4], kv[4];
            #pragma unroll
            for (int i = 0; i < 4; i++) qv[i] = sm.Qt[kk][ry * 4 + i];
            #pragma unroll
            for (int jj = 0; jj < 4; jj++) kv[jj] = sm.Kt[kk][cx * 4 + jj];
            #pragma unroll
            for (int i = 0; i < 4; i++)
                #pragma unroll
                for (int jj = 0; jj < 4; jj++)
                    sacc[i][jj] = fmaf(qv[i], kv[jj], sacc[i][jj]);
        }
        const bool diag = (j == qt);
        #pragma unroll
        for (int i = 0; i < 4; i++) {
            const int qrow = qt * FBQ + ry * 4 + i;
            #pragma unroll
            for (int jj = 0; jj < 4; jj++) {
                const int kcol = j * FBK + cx * 4 + jj;
                float sv = sacc[i][jj];
                if (diag && kcol > qrow) sv = -1e30f;
                sm.Ss[ry * 4 + i][cx * 4 + jj] = sv;
            }
        }
        __syncthreads();

        if (tid < FBQ) {
            const int r = tid;
            float mold = sm.m_s[r];
            float mnew = mold;
            #pragma unroll 8
            for (int c = 0; c < FBK; c++) mnew = fmaxf(mnew, sm.Ss[r][c]);
            const float f = __expf(mold - mnew);
            float sum = 0.0f;
            #pragma unroll 4
            for (int c = 0; c < FBK; c++) {
                float p = __expf(sm.Ss[r][c] - mnew);
                sm.Ss[r][c] = p;
                sum += p;
            }
            sm.m_s[r]  = mnew;
            sm.l_s[r]  = sm.l_s[r] * f + sum;
            sm.sc_s[r] = f;
        }
        __syncthreads();

        float fsc[4];
        #pragma unroll
        for (int i = 0; i < 4; i++) fsc[i] = sm.sc_s[ry * 4 + i];
        #pragma unroll
        for (int i = 0; i < 4; i++)
            #pragma unroll
            for (int k = 0; k < 8; k++) o[i][k] *= fsc[i];

        #pragma unroll 2
        for (int c = 0; c < FBK; c++) {
            float p[4];
            #pragma unroll
            for (int i = 0; i < 4; i++) p[i] = sm.Ss[ry * 4 + i][c];
            float4 v0 = *(const float4*)(&sm.Vs[c][cx * 8]);
            float4 v1 = *(const float4*)(&sm.Vs[c][cx * 8 + 4]);
            #pragma unroll
            for (int i = 0; i < 4; i++) {
                o[i][0] = fmaf(p[i], v0.x, o[i][0]);
                o[i][1] = fmaf(p[i], v0.y, o[i][1]);
                o[i][2] = fmaf(p[i], v0.z, o[i][2]);
                o[i][3] = fmaf(p[i], v0.w, o[i][3]);
                o[i][4] = fmaf(p[i], v1.x, o[i][4]);
                o[i][5] = fmaf(p[i], v1.y, o[i][5]);
                o[i][6] = fmaf(p[i], v1.z, o[i][6]);
                o[i][7] = fmaf(p[i], v1.w, o[i][7]);
            }
        }
    }

    #pragma unroll
    for (int i = 0; i < 4; i++) {
        const int r = ry * 4 + i;
        const float inv = 1.0f / sm.l_s[r];
        const size_t off = (rowbase + qt * FBQ + r) * DIMV + colbase + cx * 8;
        *(float4*)(g_ao + off) =
            make_float4(o[i][0] * inv, o[i][1] * inv, o[i][2] * inv, o[i][3] * inv);
        *(float4*)(g_ao + off + 4) =
            make_float4(o[i][4] * inv, o[i][5] * inv, o[i][6] * inv, o[i][7] * inv);
    }
}

// ---------------------------------------------------------------------------
extern "C" void kernel_launch(void* const* d_in, const int* in_sizes, int n_in,
                              void* d_out, int out_size)
{
    const float* x  = (const float*)d_in[0];
    const float* fc = (const float*)d_in[1];
    const float* fs = (const float*)d_in[2];
    // d_in[3] = mask (causal applied analytically)
    const float* wq = (const float*)d_in[4];
    const float* wk = (const float*)d_in[5];
    const float* wv = (const float*)d_in[6];
    const float* wo = (const float*)d_in[7];
    float* out = (float*)d_out;

    cudaFuncSetAttribute(flash_kernel,
                         cudaFuncAttributeMaxDynamicSharedMemorySize,
                         (int)sizeof(FlashSmem));
    cudaFuncSetAttribute(qkv_mma_kernel,
                         cudaFuncAttributeMaxDynamicSharedMemorySize, GSMEM);
    cudaFuncSetAttribute(oproj_mma_kernel,
                         cudaFuncAttributeMaxDynamicSharedMemorySize, GSMEM);

    // 1) transpose + split all four weights (outputs selected in-device)
    dim3 wtg(DIMV / 32, DIMV / 32, 4);
    dim3 wtb(32, 8);
    split_wT_kernel<<<wtg, wtb>>>(wq, wk, wv, wo);

    // 2) QKV projections (mma.sync + ldmatrix)
    qkv_mma_kernel<<<dim3(DIMV / BN, MROWS / BM, 3), 256, GSMEM>>>(x);

    // 3) RoPE (+ q scaling)
    const int npairs = BATCH * SEQ * NH * (HDIM / 2);
    rope_kernel<<<npairs / 256, 256>>>(fc, fs);

    // 4) Causal flash attention (fp32)
    flash_kernel<<<dim3(SEQ / FBQ, BATCH * NH), 256, sizeof(FlashSmem)>>>();

    // 5) output projection (mma.sync + ldmatrix)
    oproj_mma_kernel<<<dim3(DIMV / BN, MROWS / BM), 256, GSMEM>>>(out);
}

// round 8
// speedup vs baseline: 2.3857x; 1.6026x over previous
#include <cuda_runtime.h>
#include <cuda_bf16.h>
#include <cstdint>
#include <math.h>

// Problem constants
constexpr int BATCH = 2;
constexpr int SEQ   = 2048;
constexpr int DIMV  = 2048;
constexpr int NH    = 16;
constexpr int HDIM  = 128;
constexpr int MROWS = BATCH * SEQ;  // 4096
constexpr float QSCALE = 0.08838834764831845f;  // 1/sqrt(128)
constexpr float L2E    = 1.4426950408889634f;

// ---------------------------------------------------------------------------
// Device-global scratch. RULE (R3-R5 bug): device globals must NEVER be passed
// as kernel arguments from host code — GB300 ATS silently accepts the host
// shadow address. Reference them inside kernels only.
// ---------------------------------------------------------------------------
__device__ float g_q [MROWS * DIMV];
__device__ float g_k [MROWS * DIMV];
__device__ float g_v [MROWS * DIMV];
__device__ float g_ao[MROWS * DIMV];

// Transposed split weights: [N=2048][K=2048] K-major, value = W[k][n]
__device__ __nv_bfloat16 g_wqh[DIMV * DIMV];
__device__ __nv_bfloat16 g_wqm[DIMV * DIMV];
__device__ __nv_bfloat16 g_wkh[DIMV * DIMV];
__device__ __nv_bfloat16 g_wkm[DIMV * DIMV];
__device__ __nv_bfloat16 g_wvh[DIMV * DIMV];
__device__ __nv_bfloat16 g_wvm[DIMV * DIMV];
__device__ __nv_bfloat16 g_woh[DIMV * DIMV];
__device__ __nv_bfloat16 g_wom[DIMV * DIMV];

// ---------------------------------------------------------------------------
// helpers
// ---------------------------------------------------------------------------
__device__ __forceinline__ uint32_t smem_u32(const void* p) {
    uint32_t a;
    asm("{ .reg .u64 t; cvta.to.shared.u64 t, %1; cvt.u32.u64 %0, t; }"
        : "=r"(a) : "l"(p));
    return a;
}

__device__ __forceinline__ void mma16816(float d[4], const uint32_t a[4],
                                         const uint32_t b0, const uint32_t b1) {
    asm volatile(
        "mma.sync.aligned.m16n8k16.row.col.f32.bf16.bf16.f32 "
        "{%0,%1,%2,%3}, {%4,%5,%6,%7}, {%8,%9}, {%0,%1,%2,%3};"
        : "+f"(d[0]), "+f"(d[1]), "+f"(d[2]), "+f"(d[3])
        : "r"(a[0]), "r"(a[1]), "r"(a[2]), "r"(a[3]), "r"(b0), "r"(b1));
}

#define LDSM_X4(r0, r1, r2, r3, addr)                                  \
    asm volatile("ldmatrix.sync.aligned.m8n8.x4.shared.b16 "           \
                 "{%0,%1,%2,%3}, [%4];"                                \
                 : "=r"(r0), "=r"(r1), "=r"(r2), "=r"(r3) : "r"(addr))

#define LDSM_X4_T(r0, r1, r2, r3, addr)                                \
    asm volatile("ldmatrix.sync.aligned.m8n8.x4.trans.shared.b16 "     \
                 "{%0,%1,%2,%3}, [%4];"                                \
                 : "=r"(r0), "=r"(r1), "=r"(r2), "=r"(r3) : "r"(addr))

__device__ __forceinline__ float ex2f(float x) {
    float y;
    asm("ex2.approx.ftz.f32 %0, %1;" : "=f"(y) : "f"(x));
    return y;
}

__device__ __forceinline__ void split8(const float4& v0, const float4& v1,
                                       uint4& hi, uint4& mid)
{
    const float a[8] = {v0.x, v0.y, v0.z, v0.w, v1.x, v1.y, v1.z, v1.w};
    uint32_t h[4], m[4];
    #pragma unroll
    for (int i = 0; i < 4; i++) {
        __nv_bfloat16 hx = __float2bfloat16_rn(a[2 * i]);
        __nv_bfloat16 hy = __float2bfloat16_rn(a[2 * i + 1]);
        __nv_bfloat16 mx = __float2bfloat16_rn(a[2 * i]     - __bfloat162float(hx));
        __nv_bfloat16 my = __float2bfloat16_rn(a[2 * i + 1] - __bfloat162float(hy));
        h[i] = (uint32_t)__bfloat16_as_ushort(hx) |
               ((uint32_t)__bfloat16_as_ushort(hy) << 16);
        m[i] = (uint32_t)__bfloat16_as_ushort(mx) |
               ((uint32_t)__bfloat16_as_ushort(my) << 16);
    }
    hi  = make_uint4(h[0], h[1], h[2], h[3]);
    mid = make_uint4(m[0], m[1], m[2], m[3]);
}

// split two fp32 -> packed bf16 hi and mid (low bits = first element)
__device__ __forceinline__ void split2p(float x, float y,
                                        uint32_t& hi, uint32_t& mid) {
    __nv_bfloat16 hx = __float2bfloat16_rn(x);
    __nv_bfloat16 hy = __float2bfloat16_rn(y);
    __nv_bfloat16 mx = __float2bfloat16_rn(x - __bfloat162float(hx));
    __nv_bfloat16 my = __float2bfloat16_rn(y - __bfloat162float(hy));
    hi  = (uint32_t)__bfloat16_as_ushort(hx) |
          ((uint32_t)__bfloat16_as_ushort(hy) << 16);
    mid = (uint32_t)__bfloat16_as_ushort(mx) |
          ((uint32_t)__bfloat16_as_ushort(my) << 16);
}

// ---------------------------------------------------------------------------
// Weight transpose + split: w [K,N] fp32 -> whT, wmT [N,K] bf16.
// Output symbols selected by blockIdx.z INSIDE device code.
// ---------------------------------------------------------------------------
__global__ void split_wT_kernel(const float* __restrict__ wq,
                                const float* __restrict__ wk,
                                const float* __restrict__ wv,
                                const float* __restrict__ wo)
{
    const int z = blockIdx.z;
    const float* w = (z == 0) ? wq : (z == 1) ? wk : (z == 2) ? wv : wo;
    __nv_bfloat16* whT = (z == 0) ? g_wqh : (z == 1) ? g_wkh
                        : (z == 2) ? g_wvh : g_woh;
    __nv_bfloat16* wmT = (z == 0) ? g_wqm : (z == 1) ? g_wkm
                        : (z == 2) ? g_wvm : g_wom;

    __shared__ float t[32][33];
    const int n0 = blockIdx.x * 32;
    const int k0 = blockIdx.y * 32;
    const int tx = threadIdx.x;
    const int ty = threadIdx.y;
    #pragma unroll
    for (int i = ty; i < 32; i += 8)
        t[i][tx] = w[(size_t)(k0 + i) * DIMV + n0 + tx];
    __syncthreads();
    #pragma unroll
    for (int i = ty; i < 32; i += 8) {
        float a = t[tx][i];
        __nv_bfloat16 bh = __float2bfloat16_rn(a);
        __nv_bfloat16 bm = __float2bfloat16_rn(a - __bfloat162float(bh));
        whT[(size_t)(n0 + i) * DIMV + k0 + tx] = bh;
        wmT[(size_t)(n0 + i) * DIMV + k0 + tx] = bm;
    }
}

// ---------------------------------------------------------------------------
// mma.sync bf16 split GEMM (R7-proven, unchanged)
// ---------------------------------------------------------------------------
constexpr int BM = 128, BN = 128, BK = 32;
constexpr int RSTRB  = 80;
constexpr int TILE_B = 128 * RSTRB;
constexpr int STG_B  = 4 * TILE_B;
constexpr int GSMEM  = 2 * STG_B;
constexpr int NKSTEP = DIMV / BK;

__device__ __forceinline__ void hgemm_body(const float* __restrict__ A,
                                           const __nv_bfloat16* __restrict__ BhT,
                                           const __nv_bfloat16* __restrict__ BmT,
                                           float* __restrict__ C)
{
    extern __shared__ char smem[];
    constexpr int K = DIMV, N = DIMV;

    const int tid  = threadIdx.x;
    const int wid  = tid >> 5;
    const int lane = tid & 31;
    const int gid  = lane >> 2;
    const int tq   = lane & 3;
    const int wm   = wid & 1;
    const int wn   = wid >> 1;

    const int brow = blockIdx.y * BM;
    const int bcol = blockIdx.x * BN;

    const uint32_t sb = smem_u32(smem);

    const int la = lane & 7;
    const int lb = (lane >> 3) & 1;
    const int lc = lane >> 4;
    const uint32_t a_off = (uint32_t)(la + lb * 8) * RSTRB + lc * 16;
    const uint32_t b_off = (uint32_t)(la + lc * 8) * RSTRB + lb * 16;

    const int lrow = tid >> 1;
    const int lke  = (tid & 1) * 16;
    const uint32_t soff = (uint32_t)lrow * RSTRB + lke * 2;

    float4 pa[4];
    uint4  pbh[2], pbm[2];

    auto prefetch = [&](int kt) {
        const int k0 = kt * BK + lke;
        const float* ap = A + (size_t)(brow + lrow) * K + k0;
        pa[0] = *(const float4*)(ap);
        pa[1] = *(const float4*)(ap + 4);
        pa[2] = *(const float4*)(ap + 8);
        pa[3] = *(const float4*)(ap + 12);
        const __nv_bfloat16* bp = BhT + (size_t)(bcol + lrow) * K + k0;
        pbh[0] = *(const uint4*)(bp);
        pbh[1] = *(const uint4*)(bp + 8);
        const __nv_bfloat16* mp = BmT + (size_t)(bcol + lrow) * K + k0;
        pbm[0] = *(const uint4*)(mp);
        pbm[1] = *(const uint4*)(mp + 8);
    };

    float acc[4][4][4];
    #pragma unroll
    for (int mt = 0; mt < 4; mt++)
        #pragma unroll
        for (int nt = 0; nt < 4; nt++)
            #pragma unroll
            for (int r = 0; r < 4; r++) acc[mt][nt][r] = 0.0f;

    prefetch(0);

    #pragma unroll 1
    for (int kt = 0; kt < NKSTEP; kt++) {
        const int st = kt & 1;
        const uint32_t sAh = sb + st * STG_B;
        const uint32_t sAm = sAh + TILE_B;
        const uint32_t sBh = sAh + 2 * TILE_B;
        const uint32_t sBm = sAh + 3 * TILE_B;

        {
            uint4 ah0, am0, ah1, am1;
            split8(pa[0], pa[1], ah0, am0);
            split8(pa[2], pa[3], ah1, am1);
            char* p;
            p = smem + (st * STG_B + 0 * TILE_B) + soff;
            *(uint4*)(p) = ah0;  *(uint4*)(p + 16) = ah1;
            p = smem + (st * STG_B + 1 * TILE_B) + soff;
            *(uint4*)(p) = am0;  *(uint4*)(p + 16) = am1;
            p = smem + (st * STG_B + 2 * TILE_B) + soff;
            *(uint4*)(p) = pbh[0]; *(uint4*)(p + 16) = pbh[1];
            p = smem + (st * STG_B + 3 * TILE_B) + soff;
            *(uint4*)(p) = pbm[0]; *(uint4*)(p + 16) = pbm[1];
        }
        __syncthreads();

        if (kt + 1 < NKSTEP) prefetch(kt + 1);

        #pragma unroll
        for (int ksub = 0; ksub < 2; ksub++) {
            const uint32_t kb = ksub * 32;

            uint32_t a[4][4], bh[4][2], bm[4][2];

            #pragma unroll
            for (int mt = 0; mt < 4; mt++)
                LDSM_X4(a[mt][0], a[mt][1], a[mt][2], a[mt][3],
                        sAh + (uint32_t)(wm * 64 + mt * 16) * RSTRB + a_off + kb);
            #pragma unroll
            for (int bp = 0; bp < 2; bp++)
                LDSM_X4(bh[2 * bp][0], bh[2 * bp][1], bh[2 * bp + 1][0], bh[2 * bp + 1][1],
                        sBh + (uint32_t)(wn * 32 + bp * 16) * RSTRB + b_off + kb);

            #pragma unroll
            for (int mt = 0; mt < 4; mt++)
                #pragma unroll
                for (int nt = 0; nt < 4; nt++)
                    mma16816(acc[mt][nt], a[mt], bh[nt][0], bh[nt][1]);

            #pragma unroll
            for (int bp = 0; bp < 2; bp++)
                LDSM_X4(bm[2 * bp][0], bm[2 * bp][1], bm[2 * bp + 1][0], bm[2 * bp + 1][1],
                        sBm + (uint32_t)(wn * 32 + bp * 16) * RSTRB + b_off + kb);
            #pragma unroll
            for (int mt = 0; mt < 4; mt++)
                #pragma unroll
                for (int nt = 0; nt < 4; nt++)
                    mma16816(acc[mt][nt], a[mt], bm[nt][0], bm[nt][1]);

            #pragma unroll
            for (int mt = 0; mt < 4; mt++)
                LDSM_X4(a[mt][0], a[mt][1], a[mt][2], a[mt][3],
                        sAm + (uint32_t)(wm * 64 + mt * 16) * RSTRB + a_off + kb);
            #pragma unroll
            for (int mt = 0; mt < 4; mt++)
                #pragma unroll
                for (int nt = 0; nt < 4; nt++)
                    mma16816(acc[mt][nt], a[mt], bh[nt][0], bh[nt][1]);
        }
    }

    #pragma unroll
    for (int mt = 0; mt < 4; mt++) {
        const int row0 = brow + wm * 64 + mt * 16 + gid;
        #pragma unroll
        for (int nt = 0; nt < 4; nt++) {
            const int col = bcol + wn * 32 + nt * 8 + tq * 2;
            *(float2*)(C + (size_t)row0 * N + col) =
                make_float2(acc[mt][nt][0], acc[mt][nt][1]);
            *(float2*)(C + (size_t)(row0 + 8) * N + col) =
                make_float2(acc[mt][nt][2], acc[mt][nt][3]);
        }
    }
}

__global__ __launch_bounds__(256) void qkv_mma_kernel(const float* __restrict__ x)
{
    const __nv_bfloat16* bh = (blockIdx.z == 0) ? g_wqh : (blockIdx.z == 1) ? g_wkh : g_wvh;
    const __nv_bfloat16* bm = (blockIdx.z == 0) ? g_wqm : (blockIdx.z == 1) ? g_wkm : g_wvm;
    float* out              = (blockIdx.z == 0) ? g_q   : (blockIdx.z == 1) ? g_k   : g_v;
    hgemm_body(x, bh, bm, out);
}

__global__ __launch_bounds__(256) void oproj_mma_kernel(float* __restrict__ out)
{
    hgemm_body(g_ao, g_woh, g_wom, out);
}

// ---------------------------------------------------------------------------
// RoPE on Q (with q-scale folded in) and K, in place.
// ---------------------------------------------------------------------------
__global__ __launch_bounds__(256) void rope_kernel(const float* __restrict__ cs,
                                                   const float* __restrict__ sn)
{
    const int p = blockIdx.x * blockDim.x + threadIdx.x;
    const int d = p & 63;
    const int h = (p >> 6) & (NH - 1);
    const int s = (p >> 10) & (SEQ - 1);
    const int b = p >> 21;

    const float c  = cs[s * 64 + d];
    const float si = sn[s * 64 + d];

    const size_t off = (size_t)(b * SEQ + s) * DIMV + h * HDIM + 2 * d;

    float qr = g_q[off], qi = g_q[off + 1];
    g_q[off]     = (qr * c - qi * si) * QSCALE;
    g_q[off + 1] = (qr * si + qi * c) * QSCALE;

    float kr = g_k[off], ki = g_k[off + 1];
    g_k[off]     = kr * c - ki * si;
    g_k[off + 1] = kr * si + ki * c;
}

// ---------------------------------------------------------------------------
// Tensor-core causal flash attention.
// CTA: 128 q-rows of one (b,h); 8 warps x 16 rows. KV tiles of 64.
// S = Qh*Kh + Qh*Km + Qm*Kh ; P split hi/mid ; O += Ph*Vh + Pm*Vh + Ph*Vm.
// ---------------------------------------------------------------------------
constexpr int QSTR = 272;                       // smem row stride (256B data + 16B pad)
constexpr uint32_t FQH = 0;
constexpr uint32_t FQM = 128u * QSTR;           //  34816
constexpr uint32_t FKH = 2u * 128u * QSTR;      //  69632
constexpr uint32_t FKM = FKH + 64u * QSTR;      //  87040
constexpr uint32_t FVH = FKM + 64u * QSTR;      // 104448
constexpr uint32_t FVM = FVH + 64u * QSTR;      // 121856
constexpr int FSMEM = 139264;

__global__ __launch_bounds__(256) void flash_hmma_kernel()
{
    extern __shared__ char fsm[];
    const uint32_t sb = smem_u32(fsm);

    const int tid  = threadIdx.x;
    const int wid  = tid >> 5;
    const int lane = tid & 31;
    const int gid  = lane >> 2;
    const int tq   = lane & 3;

    const int qt = (int)gridDim.x - 1 - (int)blockIdx.x;  // big tiles first
    const int bh = blockIdx.y;
    const int b  = bh >> 4;            // NH = 16
    const int h  = bh & (NH - 1);
    const size_t rowbase = (size_t)b * SEQ;
    const int    colbase = h * HDIM;

    const int la = lane & 7;
    const int lb = (lane >> 3) & 1;
    const int lc = lane >> 4;
    const uint32_t a_off = (uint32_t)(la + lb * 8) * QSTR + lc * 16;  // A m16k16
    const uint32_t b_off = (uint32_t)(la + lc * 8) * QSTR + lb * 16;  // B n16k16 (K-major)
    const uint32_t v_off = (uint32_t)(la + lb * 8) * QSTR + lc * 16;  // B via trans (V rows=k)

    // ---- load Q tile, split hi/mid into smem (once) ----
    {
        const int r  = tid >> 1;
        const int c0 = (tid & 1) * 64;
        const float* qp = g_q + (rowbase + qt * 128 + r) * DIMV + colbase + c0;
        char* dh = fsm + FQH + (uint32_t)r * QSTR + c0 * 2;
        char* dm = fsm + FQM + (uint32_t)r * QSTR + c0 * 2;
        #pragma unroll
        for (int i = 0; i < 8; i++) {
            float4 v0 = *(const float4*)(qp + 8 * i);
            float4 v1 = *(const float4*)(qp + 8 * i + 4);
            uint4 hh, mm;
            split8(v0, v1, hh, mm);
            *(uint4*)(dh + 16 * i) = hh;
            *(uint4*)(dm + 16 * i) = mm;
        }
    }

    float o[16][4];
    #pragma unroll
    for (int i = 0; i < 16; i++)
        #pragma unroll
        for (int c = 0; c < 4; c++) o[i][c] = 0.0f;
    float m0 = -1e30f, m1 = -1e30f, l0 = 0.0f, l1 = 0.0f;

    const int row0 = qt * 128 + wid * 16 + gid;     // thread's first q row
    const int jmax = 2 * qt + 1;

    for (int j = 0; j <= jmax; j++) {
        __syncthreads();     // protect KV smem overwrite (and Q store, j=0)

        // ---- load K/V tile j, split hi/mid into smem ----
        {
            const int r  = tid >> 2;
            const int c0 = (tid & 3) * 32;
            const size_t goff = (rowbase + j * 64 + r) * DIMV + colbase + c0;
            const float* kp = g_k + goff;
            const float* vp = g_v + goff;
            char* kh = fsm + FKH + (uint32_t)r * QSTR + c0 * 2;
            char* km = fsm + FKM + (uint32_t)r * QSTR + c0 * 2;
            char* vh = fsm + FVH + (uint32_t)r * QSTR + c0 * 2;
            char* vm = fsm + FVM + (uint32_t)r * QSTR + c0 * 2;
            #pragma unroll
            for (int i = 0; i < 4; i++) {
                float4 a0 = *(const float4*)(kp + 8 * i);
                float4 a1 = *(const float4*)(kp + 8 * i + 4);
                uint4 hh, mm;
                split8(a0, a1, hh, mm);
                *(uint4*)(kh + 16 * i) = hh;
                *(uint4*)(km + 16 * i) = mm;
                float4 b0 = *(const float4*)(vp + 8 * i);
                float4 b1 = *(const float4*)(vp + 8 * i + 4);
                split8(b0, b1, hh, mm);
                *(uint4*)(vh + 16 * i) = hh;
                *(uint4*)(vm + 16 * i) = mm;
            }
        }
        __syncthreads();

        // ---- S = Q @ K^T (3-product split), fp32 acc ----
        float s[8][4];
        #pragma unroll
        for (int nt = 0; nt < 8; nt++)
            #pragma unroll
            for (int c = 0; c < 4; c++) s[nt][c] = 0.0f;

        const uint32_t qrow_off = (uint32_t)(wid * 16) * QSTR;
        #pragma unroll
        for (int t = 0; t < 8; t++) {
            const uint32_t kb = t * 32;
            uint32_t aq[4], bk[8][2], bx[8][2];

            LDSM_X4(aq[0], aq[1], aq[2], aq[3], sb + FQH + qrow_off + a_off + kb);
            #pragma unroll
            for (int np = 0; np < 4; np++)
                LDSM_X4(bk[2 * np][0], bk[2 * np][1], bk[2 * np + 1][0], bk[2 * np + 1][1],
                        sb + FKH + (uint32_t)(np * 16) * QSTR + b_off + kb);
            #pragma unroll
            for (int nt = 0; nt < 8; nt++)
                mma16816(s[nt], aq, bk[nt][0], bk[nt][1]);

            #pragma unroll
            for (int np = 0; np < 4; np++)
                LDSM_X4(bx[2 * np][0], bx[2 * np][1], bx[2 * np + 1][0], bx[2 * np + 1][1],
                        sb + FKM + (uint32_t)(np * 16) * QSTR + b_off + kb);
            #pragma unroll
            for (int nt = 0; nt < 8; nt++)
                mma16816(s[nt], aq, bx[nt][0], bx[nt][1]);

            LDSM_X4(aq[0], aq[1], aq[2], aq[3], sb + FQM + qrow_off + a_off + kb);
            #pragma unroll
            for (int nt = 0; nt < 8; nt++)
                mma16816(s[nt], aq, bk[nt][0], bk[nt][1]);
        }

        // ---- causal mask (only tiles that can clip this warp's rows) ----
        if (j * 64 + 63 > qt * 128 + wid * 16) {
            #pragma unroll
            for (int nt = 0; nt < 8; nt++) {
                const int col = j * 64 + nt * 8 + tq * 2;
                if (col     > row0)     s[nt][0] = -1e30f;
                if (col + 1 > row0)     s[nt][1] = -1e30f;
                if (col     > row0 + 8) s[nt][2] = -1e30f;
                if (col + 1 > row0 + 8) s[nt][3] = -1e30f;
            }
        }

        // ---- online softmax ----
        float mx0 = m0, mx1 = m1;
        #pragma unroll
        for (int nt = 0; nt < 8; nt++) {
            mx0 = fmaxf(mx0, fmaxf(s[nt][0], s[nt][1]));
            mx1 = fmaxf(mx1, fmaxf(s[nt][2], s[nt][3]));
        }
        mx0 = fmaxf(mx0, __shfl_xor_sync(0xffffffffu, mx0, 1));
        mx0 = fmaxf(mx0, __shfl_xor_sync(0xffffffffu, mx0, 2));
        mx1 = fmaxf(mx1, __shfl_xor_sync(0xffffffffu, mx1, 1));
        mx1 = fmaxf(mx1, __shfl_xor_sync(0xffffffffu, mx1, 2));

        const float al0 = ex2f((m0 - mx0) * L2E);
        const float al1 = ex2f((m1 - mx1) * L2E);
        m0 = mx0; m1 = mx1;

        uint32_t ph[8][2], pm[8][2];
        float sum0 = 0.0f, sum1 = 0.0f;
        #pragma unroll
        for (int nt = 0; nt < 8; nt++) {
            float p00 = ex2f((s[nt][0] - m0) * L2E);
            float p01 = ex2f((s[nt][1] - m0) * L2E);
            float p10 = ex2f((s[nt][2] - m1) * L2E);
            float p11 = ex2f((s[nt][3] - m1) * L2E);
            sum0 += p00 + p01;
            sum1 += p10 + p11;
            split2p(p00, p01, ph[nt][0], pm[nt][0]);
            split2p(p10, p11, ph[nt][1], pm[nt][1]);
        }
        sum0 += __shfl_xor_sync(0xffffffffu, sum0, 1);
        sum0 += __shfl_xor_sync(0xffffffffu, sum0, 2);
        sum1 += __shfl_xor_sync(0xffffffffu, sum1, 1);
        sum1 += __shfl_xor_sync(0xffffffffu, sum1, 2);
        l0 = l0 * al0 + sum0;
        l1 = l1 * al1 + sum1;

        #pragma unroll
        for (int i = 0; i < 16; i++) {
            o[i][0] *= al0; o[i][1] *= al0;
            o[i][2] *= al1; o[i][3] *= al1;
        }

        // ---- O += P @ V (3-product split) ----
        #pragma unroll
        for (int t = 0; t < 4; t++) {
            uint32_t aph[4] = { ph[2 * t][0], ph[2 * t][1], ph[2 * t + 1][0], ph[2 * t + 1][1] };
            uint32_t apm[4] = { pm[2 * t][0], pm[2 * t][1], pm[2 * t + 1][0], pm[2 * t + 1][1] };
            uint32_t bv[16][2];

            #pragma unroll
            for (int vn = 0; vn < 8; vn++)
                LDSM_X4_T(bv[2 * vn][0], bv[2 * vn][1], bv[2 * vn + 1][0], bv[2 * vn + 1][1],
                          sb + FVH + (uint32_t)(t * 16) * QSTR + (uint32_t)(vn * 16) * 2 + v_off);
            #pragma unroll
            for (int n = 0; n < 16; n++)
                mma16816(o[n], aph, bv[n][0], bv[n][1]);
            #pragma unroll
            for (int n = 0; n < 16; n++)
                mma16816(o[n], apm, bv[n][0], bv[n][1]);

            #pragma unroll
            for (int vn = 0; vn < 8; vn++)
                LDSM_X4_T(bv[2 * vn][0], bv[2 * vn][1], bv[2 * vn + 1][0], bv[2 * vn + 1][1],
                          sb + FVM + (uint32_t)(t * 16) * QSTR + (uint32_t)(vn * 16) * 2 + v_off);
            #pragma unroll
            for (int n = 0; n < 16; n++)
                mma16816(o[n], aph, bv[n][0], bv[n][1]);
        }
    }

    // ---- epilogue ----
    const float inv0 = 1.0f / l0;
    const float inv1 = 1.0f / l1;
    #pragma unroll
    for (int n = 0; n < 16; n++) {
        const int col = colbase + n * 8 + tq * 2;
        *(float2*)(g_ao + (rowbase + row0) * DIMV + col) =
            make_float2(o[n][0] * inv0, o[n][1] * inv0);
        *(float2*)(g_ao + (rowbase + row0 + 8) * DIMV + col) =
            make_float2(o[n][2] * inv1, o[n][3] * inv1);
    }
}

// ---------------------------------------------------------------------------
extern "C" void kernel_launch(void* const* d_in, const int* in_sizes, int n_in,
                              void* d_out, int out_size)
{
    const float* x  = (const float*)d_in[0];
    const float* fc = (const float*)d_in[1];
    const float* fs = (const float*)d_in[2];
    // d_in[3] = mask (causal applied analytically)
    const float* wq = (const float*)d_in[4];
    const float* wk = (const float*)d_in[5];
    const float* wv = (const float*)d_in[6];
    const float* wo = (const float*)d_in[7];
    float* out = (float*)d_out;

    cudaFuncSetAttribute(flash_hmma_kernel,
                         cudaFuncAttributeMaxDynamicSharedMemorySize, FSMEM);
    cudaFuncSetAttribute(qkv_mma_kernel,
                         cudaFuncAttributeMaxDynamicSharedMemorySize, GSMEM);
    cudaFuncSetAttribute(oproj_mma_kernel,
                         cudaFuncAttributeMaxDynamicSharedMemorySize, GSMEM);

    // 1) transpose + split all four weights (outputs selected in-device)
    dim3 wtg(DIMV / 32, DIMV / 32, 4);
    dim3 wtb(32, 8);
    split_wT_kernel<<<wtg, wtb>>>(wq, wk, wv, wo);

    // 2) QKV projections (mma.sync + ldmatrix)
    qkv_mma_kernel<<<dim3(DIMV / BN, MROWS / BM, 3), 256, GSMEM>>>(x);

    // 3) RoPE (+ q scaling)
    const int npairs = BATCH * SEQ * NH * (HDIM / 2);
    rope_kernel<<<npairs / 256, 256>>>(fc, fs);

    // 4) Causal flash attention (tensor cores)
    flash_hmma_kernel<<<dim3(SEQ / 128, BATCH * NH), 256, FSMEM>>>();

    // 5) output projection (mma.sync + ldmatrix)
    oproj_mma_kernel<<<dim3(DIMV / BN, MROWS / BM), 256, GSMEM>>>(out);
}

// round 9
// speedup vs baseline: 2.6752x; 1.1213x over previous
#include <cuda_runtime.h>
#include <cuda_bf16.h>
#include <cstdint>
#include <math.h>

// Problem constants
constexpr int BATCH = 2;
constexpr int SEQ   = 2048;
constexpr int DIMV  = 2048;
constexpr int NH    = 16;
constexpr int HDIM  = 128;
constexpr int MROWS = BATCH * SEQ;  // 4096
constexpr float QSCALE = 0.08838834764831845f;  // 1/sqrt(128)
constexpr float L2E    = 1.4426950408889634f;

// ---------------------------------------------------------------------------
// Device-global scratch. RULE (R3-R5 bug): device globals must NEVER be passed
// as kernel arguments from host code — GB300 ATS silently accepts the host
// shadow address. Reference them inside kernels only.
// ---------------------------------------------------------------------------
__device__ float g_q [MROWS * DIMV];   // QKV output, pre-RoPE (fp32)
__device__ float g_k [MROWS * DIMV];

__device__ __nv_bfloat16 g_xh [MROWS * DIMV];   // split x
__device__ __nv_bfloat16 g_xm [MROWS * DIMV];
__device__ __nv_bfloat16 g_qh [MROWS * DIMV];   // split roped q (scaled)
__device__ __nv_bfloat16 g_qm [MROWS * DIMV];
__device__ __nv_bfloat16 g_kh [MROWS * DIMV];   // split roped k
__device__ __nv_bfloat16 g_km [MROWS * DIMV];
__device__ __nv_bfloat16 g_vh [MROWS * DIMV];   // split v (from QKV epilogue)
__device__ __nv_bfloat16 g_vm [MROWS * DIMV];
__device__ __nv_bfloat16 g_aoh[MROWS * DIMV];   // split attention output
__device__ __nv_bfloat16 g_aom[MROWS * DIMV];

// Transposed split weights: [N=2048][K=2048] K-major, value = W[k][n]
__device__ __nv_bfloat16 g_wqh[DIMV * DIMV];
__device__ __nv_bfloat16 g_wqm[DIMV * DIMV];
__device__ __nv_bfloat16 g_wkh[DIMV * DIMV];
__device__ __nv_bfloat16 g_wkm[DIMV * DIMV];
__device__ __nv_bfloat16 g_wvh[DIMV * DIMV];
__device__ __nv_bfloat16 g_wvm[DIMV * DIMV];
__device__ __nv_bfloat16 g_woh[DIMV * DIMV];
__device__ __nv_bfloat16 g_wom[DIMV * DIMV];

// ---------------------------------------------------------------------------
// helpers
// ---------------------------------------------------------------------------
__device__ __forceinline__ uint32_t smem_u32(const void* p) {
    uint32_t a;
    asm("{ .reg .u64 t; cvta.to.shared.u64 t, %1; cvt.u32.u64 %0, t; }"
        : "=r"(a) : "l"(p));
    return a;
}

__device__ __forceinline__ void mma16816(float d[4], const uint32_t a[4],
                                         const uint32_t b0, const uint32_t b1) {
    asm volatile(
        "mma.sync.aligned.m16n8k16.row.col.f32.bf16.bf16.f32 "
        "{%0,%1,%2,%3}, {%4,%5,%6,%7}, {%8,%9}, {%0,%1,%2,%3};"
        : "+f"(d[0]), "+f"(d[1]), "+f"(d[2]), "+f"(d[3])
        : "r"(a[0]), "r"(a[1]), "r"(a[2]), "r"(a[3]), "r"(b0), "r"(b1));
}

#define LDSM_X4(r0, r1, r2, r3, addr)                                  \
    asm volatile("ldmatrix.sync.aligned.m8n8.x4.shared.b16 "           \
                 "{%0,%1,%2,%3}, [%4];"                                \
                 : "=r"(r0), "=r"(r1), "=r"(r2), "=r"(r3) : "r"(addr))

#define LDSM_X4_T(r0, r1, r2, r3, addr)                                \
    asm volatile("ldmatrix.sync.aligned.m8n8.x4.trans.shared.b16 "     \
                 "{%0,%1,%2,%3}, [%4];"                                \
                 : "=r"(r0), "=r"(r1), "=r"(r2), "=r"(r3) : "r"(addr))

#define CP16(dst, src)                                                 \
    asm volatile("cp.async.cg.shared.global [%0], [%1], 16;"           \
                 :: "r"(dst), "l"(src) : "memory")
#define CP_COMMIT() asm volatile("cp.async.commit_group;" ::: "memory")
#define CP_WAIT0()  asm volatile("cp.async.wait_group 0;"  ::: "memory")

__device__ __forceinline__ float ex2f(float x) {
    float y;
    asm("ex2.approx.ftz.f32 %0, %1;" : "=f"(y) : "f"(x));
    return y;
}

// split two fp32 -> packed bf16 hi and mid (low bits = first element)
__device__ __forceinline__ void split2p(float x, float y,
                                        uint32_t& hi, uint32_t& mid) {
    __nv_bfloat16 hx = __float2bfloat16_rn(x);
    __nv_bfloat16 hy = __float2bfloat16_rn(y);
    __nv_bfloat16 mx = __float2bfloat16_rn(x - __bfloat162float(hx));
    __nv_bfloat16 my = __float2bfloat16_rn(y - __bfloat162float(hy));
    hi  = (uint32_t)__bfloat16_as_ushort(hx) |
          ((uint32_t)__bfloat16_as_ushort(hy) << 16);
    mid = (uint32_t)__bfloat16_as_ushort(mx) |
          ((uint32_t)__bfloat16_as_ushort(my) << 16);
}

// ---------------------------------------------------------------------------
// Split x -> g_xh, g_xm (elementwise, layout preserved)
// ---------------------------------------------------------------------------
__global__ __launch_bounds__(256) void split_x_kernel(const float* __restrict__ in)
{
    const int i = blockIdx.x * blockDim.x + threadIdx.x;   // float4 index
    float4 v = ((const float4*)in)[i];
    uint32_t h0, m0, h1, m1;
    split2p(v.x, v.y, h0, m0);
    split2p(v.z, v.w, h1, m1);
    ((uint2*)g_xh)[i] = make_uint2(h0, h1);
    ((uint2*)g_xm)[i] = make_uint2(m0, m1);
}

// ---------------------------------------------------------------------------
// Weight transpose + split (R6-proven; outputs selected in-device)
// ---------------------------------------------------------------------------
__global__ void split_wT_kernel(const float* __restrict__ wq,
                                const float* __restrict__ wk,
                                const float* __restrict__ wv,
                                const float* __restrict__ wo)
{
    const int z = blockIdx.z;
    const float* w = (z == 0) ? wq : (z == 1) ? wk : (z == 2) ? wv : wo;
    __nv_bfloat16* whT = (z == 0) ? g_wqh : (z == 1) ? g_wkh
                        : (z == 2) ? g_wvh : g_woh;
    __nv_bfloat16* wmT = (z == 0) ? g_wqm : (z == 1) ? g_wkm
                        : (z == 2) ? g_wvm : g_wom;

    __shared__ float t[32][33];
    const int n0 = blockIdx.x * 32;
    const int k0 = blockIdx.y * 32;
    const int tx = threadIdx.x;
    const int ty = threadIdx.y;
    #pragma unroll
    for (int i = ty; i < 32; i += 8)
        t[i][tx] = w[(size_t)(k0 + i) * DIMV + n0 + tx];
    __syncthreads();
    #pragma unroll
    for (int i = ty; i < 32; i += 8) {
        float a = t[tx][i];
        __nv_bfloat16 bh = __float2bfloat16_rn(a);
        __nv_bfloat16 bm = __float2bfloat16_rn(a - __bfloat162float(bh));
        whT[(size_t)(n0 + i) * DIMV + k0 + tx] = bh;
        wmT[(size_t)(n0 + i) * DIMV + k0 + tx] = bm;
    }
}

// ---------------------------------------------------------------------------
// mma.sync bf16 split GEMM core: all-bf16 operands, cp.async 2-stage.
// CTA 128x128, BK=32, 8 warps (2m x 4n), warp tile 64x32, ldmatrix fragments.
// acc produced in caller-provided array; caller does the epilogue.
// ---------------------------------------------------------------------------
constexpr int BM = 128, BN = 128, BK = 32;
constexpr int RSTRB  = 80;
constexpr int TILE_B = 128 * RSTRB;        // 10240
constexpr int STG_B  = 4 * TILE_B;         // 40960 (Ah, Am, Bh, Bm)
constexpr int GSMEM  = 2 * STG_B;          // 81920 (2 stages)
constexpr int NKSTEP = DIMV / BK;          // 64

__device__ __forceinline__ void hgemm_core(const __nv_bfloat16* __restrict__ Ah,
                                           const __nv_bfloat16* __restrict__ Am,
                                           const __nv_bfloat16* __restrict__ BhT,
                                           const __nv_bfloat16* __restrict__ BmT,
                                           int brow, int bcol,
                                           float acc[4][4][4])
{
    extern __shared__ char smem[];
    constexpr int K = DIMV;
    const uint32_t sb = smem_u32(smem);

    const int tid  = threadIdx.x;
    const int wid  = tid >> 5;
    const int lane = tid & 31;
    const int wm   = wid & 1;
    const int wn   = wid >> 1;

    const int la = lane & 7;
    const int lb = (lane >> 3) & 1;
    const int lc = lane >> 4;
    const uint32_t a_off = (uint32_t)(la + lb * 8) * RSTRB + lc * 16;
    const uint32_t b_off = (uint32_t)(la + lc * 8) * RSTRB + lb * 16;

    // staging: per tile 512 x 16B chunks; per thread 2 chunks/tile
    const int srow = tid >> 1;                 // 0..127
    const int sk   = (tid & 1) * 16;           // element offset within BK
    const uint32_t sdst = (uint32_t)srow * RSTRB + (tid & 1) * 32;

    const __nv_bfloat16* srcA_h = Ah  + (size_t)(brow + srow) * K + sk;
    const __nv_bfloat16* srcA_m = Am  + (size_t)(brow + srow) * K + sk;
    const __nv_bfloat16* srcB_h = BhT + (size_t)(bcol + srow) * K + sk;
    const __nv_bfloat16* srcB_m = BmT + (size_t)(bcol + srow) * K + sk;

    auto issue = [&](int kt, int st) {
        const int k0 = kt * BK;
        const uint32_t base = sb + st * STG_B + sdst;
        CP16(base + 0 * TILE_B,      srcA_h + k0);
        CP16(base + 0 * TILE_B + 16, srcA_h + k0 + 8);
        CP16(base + 1 * TILE_B,      srcA_m + k0);
        CP16(base + 1 * TILE_B + 16, srcA_m + k0 + 8);
        CP16(base + 2 * TILE_B,      srcB_h + k0);
        CP16(base + 2 * TILE_B + 16, srcB_h + k0 + 8);
        CP16(base + 3 * TILE_B,      srcB_m + k0);
        CP16(base + 3 * TILE_B + 16, srcB_m + k0 + 8);
        CP_COMMIT();
    };

    #pragma unroll
    for (int mt = 0; mt < 4; mt++)
        #pragma unroll
        for (int nt = 0; nt < 4; nt++)
            #pragma unroll
            for (int r = 0; r < 4; r++) acc[mt][nt][r] = 0.0f;

    issue(0, 0);

    #pragma unroll 1
    for (int kt = 0; kt < NKSTEP; kt++) {
        const int st = kt & 1;
        CP_WAIT0();
        __syncthreads();
        if (kt + 1 < NKSTEP) issue(kt + 1, st ^ 1);

        const uint32_t sAh = sb + st * STG_B;
        const uint32_t sAm = sAh + TILE_B;
        const uint32_t sBh = sAh + 2 * TILE_B;
        const uint32_t sBm = sAh + 3 * TILE_B;

        #pragma unroll
        for (int ksub = 0; ksub < 2; ksub++) {
            const uint32_t kb = ksub * 32;

            uint32_t a[4][4], bh[4][2], bm[4][2];

            #pragma unroll
            for (int mt = 0; mt < 4; mt++)
                LDSM_X4(a[mt][0], a[mt][1], a[mt][2], a[mt][3],
                        sAh + (uint32_t)(wm * 64 + mt * 16) * RSTRB + a_off + kb);
            #pragma unroll
            for (int bp = 0; bp < 2; bp++)
                LDSM_X4(bh[2 * bp][0], bh[2 * bp][1], bh[2 * bp + 1][0], bh[2 * bp + 1][1],
                        sBh + (uint32_t)(wn * 32 + bp * 16) * RSTRB + b_off + kb);

            #pragma unroll
            for (int mt = 0; mt < 4; mt++)
                #pragma unroll
                for (int nt = 0; nt < 4; nt++)
                    mma16816(acc[mt][nt], a[mt], bh[nt][0], bh[nt][1]);

            #pragma unroll
            for (int bp = 0; bp < 2; bp++)
                LDSM_X4(bm[2 * bp][0], bm[2 * bp][1], bm[2 * bp + 1][0], bm[2 * bp + 1][1],
                        sBm + (uint32_t)(wn * 32 + bp * 16) * RSTRB + b_off + kb);
            #pragma unroll
            for (int mt = 0; mt < 4; mt++)
                #pragma unroll
                for (int nt = 0; nt < 4; nt++)
                    mma16816(acc[mt][nt], a[mt], bm[nt][0], bm[nt][1]);

            #pragma unroll
            for (int mt = 0; mt < 4; mt++)
                LDSM_X4(a[mt][0], a[mt][1], a[mt][2], a[mt][3],
                        sAm + (uint32_t)(wm * 64 + mt * 16) * RSTRB + a_off + kb);
            #pragma unroll
            for (int mt = 0; mt < 4; mt++)
                #pragma unroll
                for (int nt = 0; nt < 4; nt++)
                    mma16816(acc[mt][nt], a[mt], bh[nt][0], bh[nt][1]);
        }
        // write into stage st next occurs at issue(kt+2), which follows
        // iteration kt+1's __syncthreads (hazard-audited)
    }
}

// QKV: z=0 -> g_q fp32, z=1 -> g_k fp32, z=2 -> split bf16 g_vh/g_vm
__global__ __launch_bounds__(256) void qkv_mma_kernel()
{
    const int z = blockIdx.z;
    const __nv_bfloat16* bh = (z == 0) ? g_wqh : (z == 1) ? g_wkh : g_wvh;
    const __nv_bfloat16* bm = (z == 0) ? g_wqm : (z == 1) ? g_wkm : g_wvm;

    const int brow = blockIdx.y * BM;
    const int bcol = blockIdx.x * BN;

    float acc[4][4][4];
    hgemm_core(g_xh, g_xm, bh, bm, brow, bcol, acc);

    const int lane = threadIdx.x & 31;
    const int wid  = threadIdx.x >> 5;
    const int gid  = lane >> 2;
    const int tq   = lane & 3;
    const int wm   = wid & 1;
    const int wn   = wid >> 1;

    if (z < 2) {
        float* C = (z == 0) ? g_q : g_k;
        #pragma unroll
        for (int mt = 0; mt < 4; mt++) {
            const int row0 = brow + wm * 64 + mt * 16 + gid;
            #pragma unroll
            for (int nt = 0; nt < 4; nt++) {
                const int col = bcol + wn * 32 + nt * 8 + tq * 2;
                *(float2*)(C + (size_t)row0 * DIMV + col) =
                    make_float2(acc[mt][nt][0], acc[mt][nt][1]);
                *(float2*)(C + (size_t)(row0 + 8) * DIMV + col) =
                    make_float2(acc[mt][nt][2], acc[mt][nt][3]);
            }
        }
    } else {
        #pragma unroll
        for (int mt = 0; mt < 4; mt++) {
            const int row0 = brow + wm * 64 + mt * 16 + gid;
            #pragma unroll
            for (int nt = 0; nt < 4; nt++) {
                const int col = bcol + wn * 32 + nt * 8 + tq * 2;
                uint32_t h, m;
                split2p(acc[mt][nt][0], acc[mt][nt][1], h, m);
                *(uint32_t*)(g_vh + (size_t)row0 * DIMV + col) = h;
                *(uint32_t*)(g_vm + (size_t)row0 * DIMV + col) = m;
                split2p(acc[mt][nt][2], acc[mt][nt][3], h, m);
                *(uint32_t*)(g_vh + (size_t)(row0 + 8) * DIMV + col) = h;
                *(uint32_t*)(g_vm + (size_t)(row0 + 8) * DIMV + col) = m;
            }
        }
    }
}

// oproj: A = split attention output (bf16), C = harness out (fp32)
__global__ __launch_bounds__(256) void oproj_mma_kernel(float* __restrict__ out)
{
    const int brow = blockIdx.y * BM;
    const int bcol = blockIdx.x * BN;

    float acc[4][4][4];
    hgemm_core(g_aoh, g_aom, g_woh, g_wom, brow, bcol, acc);

    const int lane = threadIdx.x & 31;
    const int wid  = threadIdx.x >> 5;
    const int gid  = lane >> 2;
    const int tq   = lane & 3;
    const int wm   = wid & 1;
    const int wn   = wid >> 1;

    #pragma unroll
    for (int mt = 0; mt < 4; mt++) {
        const int row0 = brow + wm * 64 + mt * 16 + gid;
        #pragma unroll
        for (int nt = 0; nt < 4; nt++) {
            const int col = bcol + wn * 32 + nt * 8 + tq * 2;
            *(float2*)(out + (size_t)row0 * DIMV + col) =
                make_float2(acc[mt][nt][0], acc[mt][nt][1]);
            *(float2*)(out + (size_t)(row0 + 8) * DIMV + col) =
                make_float2(acc[mt][nt][2], acc[mt][nt][3]);
        }
    }
}

// ---------------------------------------------------------------------------
// RoPE: read fp32 g_q/g_k, apply rope (+QSCALE on q), write split bf16.
// ---------------------------------------------------------------------------
__global__ __launch_bounds__(256) void rope_kernel(const float* __restrict__ cs,
                                                   const float* __restrict__ sn)
{
    const int p = blockIdx.x * blockDim.x + threadIdx.x;
    const int d = p & 63;
    const int h = (p >> 6) & (NH - 1);
    const int s = (p >> 10) & (SEQ - 1);
    const int b = p >> 21;

    const float c  = cs[s * 64 + d];
    const float si = sn[s * 64 + d];

    const size_t off = (size_t)(b * SEQ + s) * DIMV + h * HDIM + 2 * d;

    float qr = g_q[off], qi = g_q[off + 1];
    float qro = (qr * c - qi * si) * QSCALE;
    float qio = (qr * si + qi * c) * QSCALE;
    uint32_t hh, mm;
    split2p(qro, qio, hh, mm);
    *(uint32_t*)(g_qh + off) = hh;
    *(uint32_t*)(g_qm + off) = mm;

    float kr = g_k[off], ki = g_k[off + 1];
    float kro = kr * c - ki * si;
    float kio = kr * si + ki * c;
    split2p(kro, kio, hh, mm);
    *(uint32_t*)(g_kh + off) = hh;
    *(uint32_t*)(g_km + off) = mm;
}

// ---------------------------------------------------------------------------
// Tensor-core causal flash attention, pre-split bf16 inputs, cp.async
// double-buffered KV. CTA: 128 q-rows x one (b,h); 8 warps x 16 rows.
// ---------------------------------------------------------------------------
constexpr int QSTR = 272;                        // row stride (256B data + 16B pad)
constexpr uint32_t FQH   = 0;
constexpr uint32_t FQM   = 128u * QSTR;          //  34816
constexpr uint32_t FKV0  = 2u * 128u * QSTR;     //  69632
constexpr uint32_t KVSTG = 4u * 64u * QSTR;      //  69632 per stage
constexpr uint32_t KVMAT = 64u * QSTR;           //  17408 per matrix
constexpr int FSMEM = (int)(FKV0 + 2 * KVSTG);   // 208896

__global__ __launch_bounds__(256) void flash_hmma_kernel()
{
    extern __shared__ char fsm[];
    const uint32_t sb = smem_u32(fsm);

    const int tid  = threadIdx.x;
    const int wid  = tid >> 5;
    const int lane = tid & 31;
    const int gid  = lane >> 2;
    const int tq   = lane & 3;

    const int qt = (int)gridDim.x - 1 - (int)blockIdx.x;  // big tiles first
    const int bh = blockIdx.y;
    const int b  = bh >> 4;
    const int h  = bh & (NH - 1);
    const size_t rowbase = (size_t)b * SEQ;
    const int    colbase = h * HDIM;

    const int la = lane & 7;
    const int lb = (lane >> 3) & 1;
    const int lc = lane >> 4;
    const uint32_t a_off = (uint32_t)(la + lb * 8) * QSTR + lc * 16;
    const uint32_t b_off = (uint32_t)(la + lc * 8) * QSTR + lb * 16;
    const uint32_t v_off = (uint32_t)(la + lb * 8) * QSTR + lc * 16;

    // staging maps
    const int qrow = tid >> 1;                    // Q: 2 threads/row
    const int qseg = (tid & 1) * 8;               // 8 segs each (16B)
    const int krow = tid >> 2;                    // KV: 4 threads/row
    const int kseg = (tid & 3) * 4;               // 4 segs each

    // ---- stage Q (both halves) + KV tile 0, one cp.async group ----
    {
        const size_t qoff = (rowbase + qt * 128 + qrow) * DIMV + colbase + qseg * 8;
        const uint32_t qdst = sb + (uint32_t)qrow * QSTR + qseg * 16;
        #pragma unroll
        for (int i = 0; i < 8; i++) {
            CP16(qdst + FQH + 16 * i, g_qh + qoff + 8 * i);
            CP16(qdst + FQM + 16 * i, g_qm + qoff + 8 * i);
        }
    }

    auto issue_kv = [&](int j, int st) {
        const size_t goff = (rowbase + j * 64 + krow) * DIMV + colbase + kseg * 8;
        const uint32_t kdst = sb + FKV0 + st * KVSTG + (uint32_t)krow * QSTR + kseg * 16;
        #pragma unroll
        for (int i = 0; i < 4; i++) {
            CP16(kdst + 0 * KVMAT + 16 * i, g_kh + goff + 8 * i);
            CP16(kdst + 1 * KVMAT + 16 * i, g_km + goff + 8 * i);
            CP16(kdst + 2 * KVMAT + 16 * i, g_vh + goff + 8 * i);
            CP16(kdst + 3 * KVMAT + 16 * i, g_vm + goff + 8 * i);
        }
        CP_COMMIT();
    };

    issue_kv(0, 0);   // Q chunks ride in this first group

    float o[16][4];
    #pragma unroll
    for (int i = 0; i < 16; i++)
        #pragma unroll
        for (int c = 0; c < 4; c++) o[i][c] = 0.0f;
    float m0 = -1e30f, m1 = -1e30f, l0 = 0.0f, l1 = 0.0f;

    const int row0 = qt * 128 + wid * 16 + gid;
    const int jmax = 2 * qt + 1;

    for (int j = 0; j <= jmax; j++) {
        const int st = j & 1;
        CP_WAIT0();
        __syncthreads();
        if (j + 1 <= jmax) issue_kv(j + 1, st ^ 1);

        const uint32_t kv = sb + FKV0 + st * KVSTG;

        // ---- S = Q @ K^T (3-product split), fp32 acc ----
        float s[8][4];
        #pragma unroll
        for (int nt = 0; nt < 8; nt++)
            #pragma unroll
            for (int c = 0; c < 4; c++) s[nt][c] = 0.0f;

        const uint32_t qrow_off = (uint32_t)(wid * 16) * QSTR;
        #pragma unroll
        for (int t = 0; t < 8; t++) {
            const uint32_t kb = t * 32;
            uint32_t aq[4], bk[8][2], bx[8][2];

            LDSM_X4(aq[0], aq[1], aq[2], aq[3], sb + FQH + qrow_off + a_off + kb);
            #pragma unroll
            for (int np = 0; np < 4; np++)
                LDSM_X4(bk[2 * np][0], bk[2 * np][1], bk[2 * np + 1][0], bk[2 * np + 1][1],
                        kv + 0 * KVMAT + (uint32_t)(np * 16) * QSTR + b_off + kb);
            #pragma unroll
            for (int nt = 0; nt < 8; nt++)
                mma16816(s[nt], aq, bk[nt][0], bk[nt][1]);

            #pragma unroll
            for (int np = 0; np < 4; np++)
                LDSM_X4(bx[2 * np][0], bx[2 * np][1], bx[2 * np + 1][0], bx[2 * np + 1][1],
                        kv + 1 * KVMAT + (uint32_t)(np * 16) * QSTR + b_off + kb);
            #pragma unroll
            for (int nt = 0; nt < 8; nt++)
                mma16816(s[nt], aq, bx[nt][0], bx[nt][1]);

            LDSM_X4(aq[0], aq[1], aq[2], aq[3], sb + FQM + qrow_off + a_off + kb);
            #pragma unroll
            for (int nt = 0; nt < 8; nt++)
                mma16816(s[nt], aq, bk[nt][0], bk[nt][1]);
        }

        // ---- causal mask ----
        if (j * 64 + 63 > qt * 128 + wid * 16) {
            #pragma unroll
            for (int nt = 0; nt < 8; nt++) {
                const int col = j * 64 + nt * 8 + tq * 2;
                if (col     > row0)     s[nt][0] = -1e30f;
                if (col + 1 > row0)     s[nt][1] = -1e30f;
                if (col     > row0 + 8) s[nt][2] = -1e30f;
                if (col + 1 > row0 + 8) s[nt][3] = -1e30f;
            }
        }

        // ---- online softmax ----
        float mx0 = m0, mx1 = m1;
        #pragma unroll
        for (int nt = 0; nt < 8; nt++) {
            mx0 = fmaxf(mx0, fmaxf(s[nt][0], s[nt][1]));
            mx1 = fmaxf(mx1, fmaxf(s[nt][2], s[nt][3]));
        }
        mx0 = fmaxf(mx0, __shfl_xor_sync(0xffffffffu, mx0, 1));
        mx0 = fmaxf(mx0, __shfl_xor_sync(0xffffffffu, mx0, 2));
        mx1 = fmaxf(mx1, __shfl_xor_sync(0xffffffffu, mx1, 1));
        mx1 = fmaxf(mx1, __shfl_xor_sync(0xffffffffu, mx1, 2));

        const float al0 = ex2f((m0 - mx0) * L2E);
        const float al1 = ex2f((m1 - mx1) * L2E);
        m0 = mx0; m1 = mx1;

        uint32_t ph[8][2], pm[8][2];
        float sum0 = 0.0f, sum1 = 0.0f;
        #pragma unroll
        for (int nt = 0; nt < 8; nt++) {
            float p00 = ex2f((s[nt][0] - m0) * L2E);
            float p01 = ex2f((s[nt][1] - m0) * L2E);
            float p10 = ex2f((s[nt][2] - m1) * L2E);
            float p11 = ex2f((s[nt][3] - m1) * L2E);
            sum0 += p00 + p01;
            sum1 += p10 + p11;
            split2p(p00, p01, ph[nt][0], pm[nt][0]);
            split2p(p10, p11, ph[nt][1], pm[nt][1]);
        }
        sum0 += __shfl_xor_sync(0xffffffffu, sum0, 1);
        sum0 += __shfl_xor_sync(0xffffffffu, sum0, 2);
        sum1 += __shfl_xor_sync(0xffffffffu, sum1, 1);
        sum1 += __shfl_xor_sync(0xffffffffu, sum1, 2);
        l0 = l0 * al0 + sum0;
        l1 = l1 * al1 + sum1;

        #pragma unroll
        for (int i = 0; i < 16; i++) {
            o[i][0] *= al0; o[i][1] *= al0;
            o[i][2] *= al1; o[i][3] *= al1;
        }

        // ---- O += P @ V (3-product split) ----
        #pragma unroll
        for (int t = 0; t < 4; t++) {
            uint32_t aph[4] = { ph[2 * t][0], ph[2 * t][1], ph[2 * t + 1][0], ph[2 * t + 1][1] };
            uint32_t apm[4] = { pm[2 * t][0], pm[2 * t][1], pm[2 * t + 1][0], pm[2 * t + 1][1] };
            uint32_t bv[16][2];

            #pragma unroll
            for (int vn = 0; vn < 8; vn++)
                LDSM_X4_T(bv[2 * vn][0], bv[2 * vn][1], bv[2 * vn + 1][0], bv[2 * vn + 1][1],
                          kv + 2 * KVMAT + (uint32_t)(t * 16) * QSTR + (uint32_t)(vn * 16) * 2 + v_off);
            #pragma unroll
            for (int n = 0; n < 16; n++)
                mma16816(o[n], aph, bv[n][0], bv[n][1]);
            #pragma unroll
            for (int n = 0; n < 16; n++)
                mma16816(o[n], apm, bv[n][0], bv[n][1]);

            #pragma unroll
            for (int vn = 0; vn < 8; vn++)
                LDSM_X4_T(bv[2 * vn][0], bv[2 * vn][1], bv[2 * vn + 1][0], bv[2 * vn + 1][1],
                          kv + 3 * KVMAT + (uint32_t)(t * 16) * QSTR + (uint32_t)(vn * 16) * 2 + v_off);
            #pragma unroll
            for (int n = 0; n < 16; n++)
                mma16816(o[n], aph, bv[n][0], bv[n][1]);
        }
    }

    // ---- epilogue: write split bf16 attention output ----
    const float inv0 = 1.0f / l0;
    const float inv1 = 1.0f / l1;
    #pragma unroll
    for (int n = 0; n < 16; n++) {
        const int col = colbase + n * 8 + tq * 2;
        uint32_t hh, mm;
        split2p(o[n][0] * inv0, o[n][1] * inv0, hh, mm);
        *(uint32_t*)(g_aoh + (rowbase + row0) * DIMV + col) = hh;
        *(uint32_t*)(g_aom + (rowbase + row0) * DIMV + col) = mm;
        split2p(o[n][2] * inv1, o[n][3] * inv1, hh, mm);
        *(uint32_t*)(g_aoh + (rowbase + row0 + 8) * DIMV + col) = hh;
        *(uint32_t*)(g_aom + (rowbase + row0 + 8) * DIMV + col) = mm;
    }
}

// ---------------------------------------------------------------------------
extern "C" void kernel_launch(void* const* d_in, const int* in_sizes, int n_in,
                              void* d_out, int out_size)
{
    const float* x  = (const float*)d_in[0];
    const float* fc = (const float*)d_in[1];
    const float* fs = (const float*)d_in[2];
    // d_in[3] = mask (causal applied analytically)
    const float* wq = (const float*)d_in[4];
    const float* wk = (const float*)d_in[5];
    const float* wv = (const float*)d_in[6];
    const float* wo = (const float*)d_in[7];
    float* out = (float*)d_out;

    cudaFuncSetAttribute(flash_hmma_kernel,
                         cudaFuncAttributeMaxDynamicSharedMemorySize, FSMEM);
    cudaFuncSetAttribute(qkv_mma_kernel,
                         cudaFuncAttributeMaxDynamicSharedMemorySize, GSMEM);
    cudaFuncSetAttribute(oproj_mma_kernel,
                         cudaFuncAttributeMaxDynamicSharedMemorySize, GSMEM);

    // 1) split inputs + weights
    split_x_kernel<<<MROWS * DIMV / 4 / 256, 256>>>(x);
    dim3 wtg(DIMV / 32, DIMV / 32, 4);
    dim3 wtb(32, 8);
    split_wT_kernel<<<wtg, wtb>>>(wq, wk, wv, wo);

    // 2) QKV projections (all-bf16, cp.async pipeline)
    qkv_mma_kernel<<<dim3(DIMV / BN, MROWS / BM, 3), 256, GSMEM>>>();

    // 3) RoPE (+ q scaling) -> split bf16 q,k
    const int npairs = BATCH * SEQ * NH * (HDIM / 2);
    rope_kernel<<<npairs / 256, 256>>>(fc, fs);

    // 4) Causal flash attention (tensor cores, cp.async KV pipeline)
    flash_hmma_kernel<<<dim3(SEQ / 128, BATCH * NH), 256, FSMEM>>>();

    // 5) output projection
    oproj_mma_kernel<<<dim3(DIMV / BN, MROWS / BM), 256, GSMEM>>>(out);
}

// round 10
// speedup vs baseline: 3.6745x; 1.3736x over previous
#include <cuda_runtime.h>
#include <cuda_fp16.h>
#include <cstdint>
#include <math.h>

// Problem constants
constexpr int BATCH = 2;
constexpr int SEQ   = 2048;
constexpr int DIMV  = 2048;
constexpr int NH    = 16;
constexpr int HDIM  = 128;
constexpr int MROWS = BATCH * SEQ;  // 4096
constexpr float QSCALE = 0.08838834764831845f;  // 1/sqrt(128)
constexpr float L2E    = 1.4426950408889634f;

// ---------------------------------------------------------------------------
// Device-global scratch. RULE (R3-R5 bug): device globals must NEVER be passed
// as kernel arguments from host code — GB300 ATS silently accepts the host
// shadow address. Reference them inside kernels only.
// ---------------------------------------------------------------------------
__device__ __half g_xh [MROWS * DIMV];   // fp16(x)            (A side, hi only)
__device__ __half g_qh [MROWS * DIMV];   // fp16(roped,scaled q)
__device__ __half g_kh [MROWS * DIMV];   // roped k hi
__device__ __half g_km [MROWS * DIMV];   // roped k mid
__device__ __half g_vh [MROWS * DIMV];   // v hi
__device__ __half g_vm [MROWS * DIMV];   // v mid
__device__ __half g_aoh[MROWS * DIMV];   // fp16(attention out) (A side, hi only)

// Transposed split weights: [N=2048][K=2048] K-major, value = W[k][n]
__device__ __half g_wqh[DIMV * DIMV];
__device__ __half g_wqm[DIMV * DIMV];
__device__ __half g_wkh[DIMV * DIMV];
__device__ __half g_wkm[DIMV * DIMV];
__device__ __half g_wvh[DIMV * DIMV];
__device__ __half g_wvm[DIMV * DIMV];
__device__ __half g_woh[DIMV * DIMV];
__device__ __half g_wom[DIMV * DIMV];

// ---------------------------------------------------------------------------
// helpers
// ---------------------------------------------------------------------------
__device__ __forceinline__ uint32_t smem_u32(const void* p) {
    uint32_t a;
    asm("{ .reg .u64 t; cvta.to.shared.u64 t, %1; cvt.u32.u64 %0, t; }"
        : "=r"(a) : "l"(p));
    return a;
}

__device__ __forceinline__ void mma16816(float d[4], const uint32_t a[4],
                                         const uint32_t b0, const uint32_t b1) {
    asm volatile(
        "mma.sync.aligned.m16n8k16.row.col.f32.f16.f16.f32 "
        "{%0,%1,%2,%3}, {%4,%5,%6,%7}, {%8,%9}, {%0,%1,%2,%3};"
        : "+f"(d[0]), "+f"(d[1]), "+f"(d[2]), "+f"(d[3])
        : "r"(a[0]), "r"(a[1]), "r"(a[2]), "r"(a[3]), "r"(b0), "r"(b1));
}

#define LDSM_X4(r0, r1, r2, r3, addr)                                  \
    asm volatile("ldmatrix.sync.aligned.m8n8.x4.shared.b16 "           \
                 "{%0,%1,%2,%3}, [%4];"                                \
                 : "=r"(r0), "=r"(r1), "=r"(r2), "=r"(r3) : "r"(addr))

#define LDSM_X4_T(r0, r1, r2, r3, addr)                                \
    asm volatile("ldmatrix.sync.aligned.m8n8.x4.trans.shared.b16 "     \
                 "{%0,%1,%2,%3}, [%4];"                                \
                 : "=r"(r0), "=r"(r1), "=r"(r2), "=r"(r3) : "r"(addr))

#define CP16(dst, src)                                                 \
    asm volatile("cp.async.cg.shared.global [%0], [%1], 16;"           \
                 :: "r"(dst), "l"(src) : "memory")
#define CP_COMMIT()  asm volatile("cp.async.commit_group;" ::: "memory")
#define CP_WAITG(n)  asm volatile("cp.async.wait_group %0;" :: "n"(n) : "memory")

__device__ __forceinline__ float ex2f(float x) {
    float y;
    asm("ex2.approx.ftz.f32 %0, %1;" : "=f"(y) : "f"(x));
    return y;
}

__device__ __forceinline__ uint32_t pack_h2(float x, float y) {
    __half2 h = __floats2half2_rn(x, y);
    return *reinterpret_cast<uint32_t*>(&h);
}

// split two fp32 -> packed fp16 hi and mid
__device__ __forceinline__ void split2h(float x, float y,
                                        uint32_t& hi, uint32_t& mid) {
    __half hx = __float2half_rn(x);
    __half hy = __float2half_rn(y);
    __half mx = __float2half_rn(x - __half2float(hx));
    __half my = __float2half_rn(y - __half2float(hy));
    hi  = (uint32_t)__half_as_ushort(hx) |
          ((uint32_t)__half_as_ushort(hy) << 16);
    mid = (uint32_t)__half_as_ushort(mx) |
          ((uint32_t)__half_as_ushort(my) << 16);
}

// ---------------------------------------------------------------------------
// Split x -> g_xh (fp16 hi only)
// ---------------------------------------------------------------------------
__global__ __launch_bounds__(256) void split_x_kernel(const float* __restrict__ in)
{
    const int i = blockIdx.x * blockDim.x + threadIdx.x;   // float4 index
    float4 v = ((const float4*)in)[i];
    ((uint2*)g_xh)[i] = make_uint2(pack_h2(v.x, v.y), pack_h2(v.z, v.w));
}

// ---------------------------------------------------------------------------
// Weight transpose + split: w [K,N] fp32 -> whT, wmT [N,K] fp16 (hi + mid).
// Output symbols selected by blockIdx.z INSIDE device code.
// ---------------------------------------------------------------------------
__global__ void split_wT_kernel(const float* __restrict__ wq,
                                const float* __restrict__ wk,
                                const float* __restrict__ wv,
                                const float* __restrict__ wo)
{
    const int z = blockIdx.z;
    const float* w = (z == 0) ? wq : (z == 1) ? wk : (z == 2) ? wv : wo;
    __half* whT = (z == 0) ? g_wqh : (z == 1) ? g_wkh : (z == 2) ? g_wvh : g_woh;
    __half* wmT = (z == 0) ? g_wqm : (z == 1) ? g_wkm : (z == 2) ? g_wvm : g_wom;

    __shared__ float t[32][33];
    const int n0 = blockIdx.x * 32;
    const int k0 = blockIdx.y * 32;
    const int tx = threadIdx.x;
    const int ty = threadIdx.y;
    #pragma unroll
    for (int i = ty; i < 32; i += 8)
        t[i][tx] = w[(size_t)(k0 + i) * DIMV + n0 + tx];
    __syncthreads();
    #pragma unroll
    for (int i = ty; i < 32; i += 8) {
        float a = t[tx][i];
        __half bh = __float2half_rn(a);
        __half bm = __float2half_rn(a - __half2float(bh));
        whT[(size_t)(n0 + i) * DIMV + k0 + tx] = bh;
        wmT[(size_t)(n0 + i) * DIMV + k0 + tx] = bm;
    }
}

// ---------------------------------------------------------------------------
// fp16 2-product GEMM core: D = Ah*(Bh+Bm). cp.async 3-stage pipeline.
// CTA 128x128, BK=32, 8 warps (2m x 4n), warp tile 64x32, ldmatrix fragments.
// ---------------------------------------------------------------------------
constexpr int BM = 128, BN = 128, BK = 32;
constexpr int RSTRB  = 80;
constexpr int TILE_B = 128 * RSTRB;        // 10240
constexpr int STG_B  = 3 * TILE_B;         // 30720 (Ah, Bh, Bm)
constexpr int NSTAGE = 3;
constexpr int GSMEM  = NSTAGE * STG_B;     // 92160
constexpr int NKSTEP = DIMV / BK;          // 64

__device__ __forceinline__ void hgemm_core(const __half* __restrict__ Ah,
                                           const __half* __restrict__ BhT,
                                           const __half* __restrict__ BmT,
                                           int brow, int bcol,
                                           float acc[4][4][4])
{
    extern __shared__ char smem[];
    constexpr int K = DIMV;
    const uint32_t sb = smem_u32(smem);

    const int tid  = threadIdx.x;
    const int wid  = tid >> 5;
    const int lane = tid & 31;
    const int wm   = wid & 1;
    const int wn   = wid >> 1;

    const int la = lane & 7;
    const int lb = (lane >> 3) & 1;
    const int lc = lane >> 4;
    const uint32_t a_off = (uint32_t)(la + lb * 8) * RSTRB + lc * 16;
    const uint32_t b_off = (uint32_t)(la + lc * 8) * RSTRB + lb * 16;

    const int srow = tid >> 1;
    const int sk   = (tid & 1) * 16;
    const uint32_t sdst = (uint32_t)srow * RSTRB + (tid & 1) * 32;

    const __half* srcA = Ah  + (size_t)(brow + srow) * K + sk;
    const __half* srcBh = BhT + (size_t)(bcol + srow) * K + sk;
    const __half* srcBm = BmT + (size_t)(bcol + srow) * K + sk;

    auto issue = [&](int kt) {
        const int k0 = kt * BK;
        const uint32_t base = sb + (kt % NSTAGE) * STG_B + sdst;
        CP16(base + 0 * TILE_B,      srcA  + k0);
        CP16(base + 0 * TILE_B + 16, srcA  + k0 + 8);
        CP16(base + 1 * TILE_B,      srcBh + k0);
        CP16(base + 1 * TILE_B + 16, srcBh + k0 + 8);
        CP16(base + 2 * TILE_B,      srcBm + k0);
        CP16(base + 2 * TILE_B + 16, srcBm + k0 + 8);
        CP_COMMIT();
    };

    #pragma unroll
    for (int mt = 0; mt < 4; mt++)
        #pragma unroll
        for (int nt = 0; nt < 4; nt++)
            #pragma unroll
            for (int r = 0; r < 4; r++) acc[mt][nt][r] = 0.0f;

    issue(0);
    issue(1);

    #pragma unroll 1
    for (int kt = 0; kt < NKSTEP; kt++) {
        CP_WAITG(1);
        __syncthreads();
        if (kt + 2 < NKSTEP) issue(kt + 2);

        const uint32_t sAh = sb + (kt % NSTAGE) * STG_B;
        const uint32_t sBh = sAh + TILE_B;
        const uint32_t sBm = sAh + 2 * TILE_B;

        #pragma unroll
        for (int ksub = 0; ksub < 2; ksub++) {
            const uint32_t kb = ksub * 32;

            uint32_t a[4][4], bh[4][2], bm[4][2];

            #pragma unroll
            for (int mt = 0; mt < 4; mt++)
                LDSM_X4(a[mt][0], a[mt][1], a[mt][2], a[mt][3],
                        sAh + (uint32_t)(wm * 64 + mt * 16) * RSTRB + a_off + kb);
            #pragma unroll
            for (int bp = 0; bp < 2; bp++)
                LDSM_X4(bh[2 * bp][0], bh[2 * bp][1], bh[2 * bp + 1][0], bh[2 * bp + 1][1],
                        sBh + (uint32_t)(wn * 32 + bp * 16) * RSTRB + b_off + kb);
            #pragma unroll
            for (int mt = 0; mt < 4; mt++)
                #pragma unroll
                for (int nt = 0; nt < 4; nt++)
                    mma16816(acc[mt][nt], a[mt], bh[nt][0], bh[nt][1]);

            #pragma unroll
            for (int bp = 0; bp < 2; bp++)
                LDSM_X4(bm[2 * bp][0], bm[2 * bp][1], bm[2 * bp + 1][0], bm[2 * bp + 1][1],
                        sBm + (uint32_t)(wn * 32 + bp * 16) * RSTRB + b_off + kb);
            #pragma unroll
            for (int mt = 0; mt < 4; mt++)
                #pragma unroll
                for (int nt = 0; nt < 4; nt++)
                    mma16816(acc[mt][nt], a[mt], bm[nt][0], bm[nt][1]);
        }
        // stage reuse protected by the __syncthreads of later iterations
    }
}

// QKV with fused RoPE epilogue. z=0 -> roped+scaled q (hi), z=1 -> roped k
// (hi+mid), z=2 -> v (hi+mid).
__global__ __launch_bounds__(256) void qkv_mma_kernel(const float* __restrict__ fc,
                                                      const float* __restrict__ fs)
{
    const int z = blockIdx.z;
    const __half* bh = (z == 0) ? g_wqh : (z == 1) ? g_wkh : g_wvh;
    const __half* bm = (z == 0) ? g_wqm : (z == 1) ? g_wkm : g_wvm;

    const int brow = blockIdx.y * BM;
    const int bcol = blockIdx.x * BN;

    float acc[4][4][4];
    hgemm_core(g_xh, bh, bm, brow, bcol, acc);

    const int lane = threadIdx.x & 31;
    const int wid  = threadIdx.x >> 5;
    const int gid  = lane >> 2;
    const int tq   = lane & 3;
    const int wm   = wid & 1;
    const int wn   = wid >> 1;

    #pragma unroll
    for (int mt = 0; mt < 4; mt++) {
        const int row0 = brow + wm * 64 + mt * 16 + gid;   // and row0+8
        #pragma unroll
        for (int nt = 0; nt < 4; nt++) {
            const int col = bcol + wn * 32 + nt * 8 + tq * 2;
            const size_t o0 = (size_t)row0 * DIMV + col;
            const size_t o1 = (size_t)(row0 + 8) * DIMV + col;

            if (z == 2) {
                uint32_t h, m;
                split2h(acc[mt][nt][0], acc[mt][nt][1], h, m);
                *(uint32_t*)(g_vh + o0) = h;
                *(uint32_t*)(g_vm + o0) = m;
                split2h(acc[mt][nt][2], acc[mt][nt][3], h, m);
                *(uint32_t*)(g_vh + o1) = h;
                *(uint32_t*)(g_vm + o1) = m;
            } else {
                const int d  = (col & (HDIM - 1)) >> 1;
                const int s0 = row0 & (SEQ - 1);
                const int s1 = (row0 + 8) & (SEQ - 1);
                const float c0 = fc[s0 * 64 + d], n0 = fs[s0 * 64 + d];
                const float c1 = fc[s1 * 64 + d], n1 = fs[s1 * 64 + d];
                float r0 = acc[mt][nt][0] * c0 - acc[mt][nt][1] * n0;
                float i0 = acc[mt][nt][0] * n0 + acc[mt][nt][1] * c0;
                float r1 = acc[mt][nt][2] * c1 - acc[mt][nt][3] * n1;
                float i1 = acc[mt][nt][2] * n1 + acc[mt][nt][3] * c1;
                if (z == 0) {
                    *(uint32_t*)(g_qh + o0) = pack_h2(r0 * QSCALE, i0 * QSCALE);
                    *(uint32_t*)(g_qh + o1) = pack_h2(r1 * QSCALE, i1 * QSCALE);
                } else {
                    uint32_t h, m;
                    split2h(r0, i0, h, m);
                    *(uint32_t*)(g_kh + o0) = h;
                    *(uint32_t*)(g_km + o0) = m;
                    split2h(r1, i1, h, m);
                    *(uint32_t*)(g_kh + o1) = h;
                    *(uint32_t*)(g_km + o1) = m;
                }
            }
        }
    }
}

// oproj: A = attention out (fp16 hi), C = harness out (fp32)
__global__ __launch_bounds__(256) void oproj_mma_kernel(float* __restrict__ out)
{
    const int brow = blockIdx.y * BM;
    const int bcol = blockIdx.x * BN;

    float acc[4][4][4];
    hgemm_core(g_aoh, g_woh, g_wom, brow, bcol, acc);

    const int lane = threadIdx.x & 31;
    const int wid  = threadIdx.x >> 5;
    const int gid  = lane >> 2;
    const int tq   = lane & 3;
    const int wm   = wid & 1;
    const int wn   = wid >> 1;

    #pragma unroll
    for (int mt = 0; mt < 4; mt++) {
        const int row0 = brow + wm * 64 + mt * 16 + gid;
        #pragma unroll
        for (int nt = 0; nt < 4; nt++) {
            const int col = bcol + wn * 32 + nt * 8 + tq * 2;
            *(float2*)(out + (size_t)row0 * DIMV + col) =
                make_float2(acc[mt][nt][0], acc[mt][nt][1]);
            *(float2*)(out + (size_t)(row0 + 8) * DIMV + col) =
                make_float2(acc[mt][nt][2], acc[mt][nt][3]);
        }
    }
}

// ---------------------------------------------------------------------------
// Tensor-core causal flash attention, fp16 2-product.
// CTA: 128 q-rows x one (b,h); 8 warps x 16 rows; KV tiles of 64,
// cp.async double-buffered. S = Qh*(Kh+Km); O += Ph*(Vh+Vm).
// ---------------------------------------------------------------------------
constexpr int QSTR = 272;                        // row stride (256B data + 16B pad)
constexpr uint32_t FQH   = 0;
constexpr uint32_t FKV0  = 128u * QSTR;          //  34816
constexpr uint32_t KVMAT = 64u * QSTR;           //  17408 per matrix
constexpr uint32_t KVSTG = 4u * KVMAT;           //  69632 per stage (Kh,Km,Vh,Vm)
constexpr int FSMEM = (int)(FKV0 + 2 * KVSTG);   // 174080

__global__ __launch_bounds__(256) void flash_hmma_kernel()
{
    extern __shared__ char fsm[];
    const uint32_t sb = smem_u32(fsm);

    const int tid  = threadIdx.x;
    const int wid  = tid >> 5;
    const int lane = tid & 31;
    const int gid  = lane >> 2;
    const int tq   = lane & 3;

    const int qt = (int)gridDim.x - 1 - (int)blockIdx.x;  // big tiles first
    const int bh = blockIdx.y;
    const int b  = bh >> 4;
    const int h  = bh & (NH - 1);
    const size_t rowbase = (size_t)b * SEQ;
    const int    colbase = h * HDIM;

    const int la = lane & 7;
    const int lb = (lane >> 3) & 1;
    const int lc = lane >> 4;
    const uint32_t a_off = (uint32_t)(la + lb * 8) * QSTR + lc * 16;
    const uint32_t b_off = (uint32_t)(la + lc * 8) * QSTR + lb * 16;
    const uint32_t v_off = (uint32_t)(la + lb * 8) * QSTR + lc * 16;

    const int qrow = tid >> 1;
    const int qseg = (tid & 1) * 8;
    const int krow = tid >> 2;
    const int kseg = (tid & 3) * 4;

    // ---- stage Q (hi) + KV tile 0 in one group ----
    {
        const size_t qoff = (rowbase + qt * 128 + qrow) * DIMV + colbase + qseg * 8;
        const uint32_t qdst = sb + FQH + (uint32_t)qrow * QSTR + qseg * 16;
        #pragma unroll
        for (int i = 0; i < 8; i++)
            CP16(qdst + 16 * i, g_qh + qoff + 8 * i);
    }

    auto issue_kv = [&](int j, int st) {
        const size_t goff = (rowbase + j * 64 + krow) * DIMV + colbase + kseg * 8;
        const uint32_t kdst = sb + FKV0 + st * KVSTG + (uint32_t)krow * QSTR + kseg * 16;
        #pragma unroll
        for (int i = 0; i < 4; i++) {
            CP16(kdst + 0 * KVMAT + 16 * i, g_kh + goff + 8 * i);
            CP16(kdst + 1 * KVMAT + 16 * i, g_km + goff + 8 * i);
            CP16(kdst + 2 * KVMAT + 16 * i, g_vh + goff + 8 * i);
            CP16(kdst + 3 * KVMAT + 16 * i, g_vm + goff + 8 * i);
        }
        CP_COMMIT();
    };

    issue_kv(0, 0);

    float o[16][4];
    #pragma unroll
    for (int i = 0; i < 16; i++)
        #pragma unroll
        for (int c = 0; c < 4; c++) o[i][c] = 0.0f;
    float m0 = -1e30f, m1 = -1e30f, l0 = 0.0f, l1 = 0.0f;

    const int row0 = qt * 128 + wid * 16 + gid;
    const int jmax = 2 * qt + 1;

    for (int j = 0; j <= jmax; j++) {
        const int st = j & 1;
        CP_WAITG(0);
        __syncthreads();
        if (j + 1 <= jmax) issue_kv(j + 1, st ^ 1);

        const uint32_t kv = sb + FKV0 + st * KVSTG;

        // ---- S = Qh @ (Kh + Km)^T ----
        float s[8][4];
        #pragma unroll
        for (int nt = 0; nt < 8; nt++)
            #pragma unroll
            for (int c = 0; c < 4; c++) s[nt][c] = 0.0f;

        const uint32_t qrow_off = (uint32_t)(wid * 16) * QSTR;
        #pragma unroll
        for (int t = 0; t < 8; t++) {
            const uint32_t kb = t * 32;
            uint32_t aq[4], bk[8][2];

            LDSM_X4(aq[0], aq[1], aq[2], aq[3], sb + FQH + qrow_off + a_off + kb);
            #pragma unroll
            for (int np = 0; np < 4; np++)
                LDSM_X4(bk[2 * np][0], bk[2 * np][1], bk[2 * np + 1][0], bk[2 * np + 1][1],
                        kv + 0 * KVMAT + (uint32_t)(np * 16) * QSTR + b_off + kb);
            #pragma unroll
            for (int nt = 0; nt < 8; nt++)
                mma16816(s[nt], aq, bk[nt][0], bk[nt][1]);

            #pragma unroll
            for (int np = 0; np < 4; np++)
                LDSM_X4(bk[2 * np][0], bk[2 * np][1], bk[2 * np + 1][0], bk[2 * np + 1][1],
                        kv + 1 * KVMAT + (uint32_t)(np * 16) * QSTR + b_off + kb);
            #pragma unroll
            for (int nt = 0; nt < 8; nt++)
                mma16816(s[nt], aq, bk[nt][0], bk[nt][1]);
        }

        // ---- causal mask ----
        if (j * 64 + 63 > qt * 128 + wid * 16) {
            #pragma unroll
            for (int nt = 0; nt < 8; nt++) {
                const int col = j * 64 + nt * 8 + tq * 2;
                if (col     > row0)     s[nt][0] = -1e30f;
                if (col + 1 > row0)     s[nt][1] = -1e30f;
                if (col     > row0 + 8) s[nt][2] = -1e30f;
                if (col + 1 > row0 + 8) s[nt][3] = -1e30f;
            }
        }

        // ---- online softmax ----
        float mx0 = m0, mx1 = m1;
        #pragma unroll
        for (int nt = 0; nt < 8; nt++) {
            mx0 = fmaxf(mx0, fmaxf(s[nt][0], s[nt][1]));
            mx1 = fmaxf(mx1, fmaxf(s[nt][2], s[nt][3]));
        }
        mx0 = fmaxf(mx0, __shfl_xor_sync(0xffffffffu, mx0, 1));
        mx0 = fmaxf(mx0, __shfl_xor_sync(0xffffffffu, mx0, 2));
        mx1 = fmaxf(mx1, __shfl_xor_sync(0xffffffffu, mx1, 1));
        mx1 = fmaxf(mx1, __shfl_xor_sync(0xffffffffu, mx1, 2));

        const float al0 = ex2f((m0 - mx0) * L2E);
        const float al1 = ex2f((m1 - mx1) * L2E);
        m0 = mx0; m1 = mx1;

        uint32_t ph[8][2];
        float sum0 = 0.0f, sum1 = 0.0f;
        #pragma unroll
        for (int nt = 0; nt < 8; nt++) {
            float p00 = ex2f((s[nt][0] - m0) * L2E);
            float p01 = ex2f((s[nt][1] - m0) * L2E);
            float p10 = ex2f((s[nt][2] - m1) * L2E);
            float p11 = ex2f((s[nt][3] - m1) * L2E);
            sum0 += p00 + p01;
            sum1 += p10 + p11;
            ph[nt][0] = pack_h2(p00, p01);
            ph[nt][1] = pack_h2(p10, p11);
        }
        sum0 += __shfl_xor_sync(0xffffffffu, sum0, 1);
        sum0 += __shfl_xor_sync(0xffffffffu, sum0, 2);
        sum1 += __shfl_xor_sync(0xffffffffu, sum1, 1);
        sum1 += __shfl_xor_sync(0xffffffffu, sum1, 2);
        l0 = l0 * al0 + sum0;
        l1 = l1 * al1 + sum1;

        #pragma unroll
        for (int i = 0; i < 16; i++) {
            o[i][0] *= al0; o[i][1] *= al0;
            o[i][2] *= al1; o[i][3] *= al1;
        }

        // ---- O += Ph @ (Vh + Vm) ----
        #pragma unroll
        for (int t = 0; t < 4; t++) {
            uint32_t aph[4] = { ph[2 * t][0], ph[2 * t][1], ph[2 * t + 1][0], ph[2 * t + 1][1] };
            uint32_t bv[16][2];

            #pragma unroll
            for (int vn = 0; vn < 8; vn++)
                LDSM_X4_T(bv[2 * vn][0], bv[2 * vn][1], bv[2 * vn + 1][0], bv[2 * vn + 1][1],
                          kv + 2 * KVMAT + (uint32_t)(t * 16) * QSTR + (uint32_t)(vn * 16) * 2 + v_off);
            #pragma unroll
            for (int n = 0; n < 16; n++)
                mma16816(o[n], aph, bv[n][0], bv[n][1]);

            #pragma unroll
            for (int vn = 0; vn < 8; vn++)
                LDSM_X4_T(bv[2 * vn][0], bv[2 * vn][1], bv[2 * vn + 1][0], bv[2 * vn + 1][1],
                          kv + 3 * KVMAT + (uint32_t)(t * 16) * QSTR + (uint32_t)(vn * 16) * 2 + v_off);
            #pragma unroll
            for (int n = 0; n < 16; n++)
                mma16816(o[n], aph, bv[n][0], bv[n][1]);
        }
    }

    // ---- epilogue: write fp16 (hi) attention output ----
    const float inv0 = 1.0f / l0;
    const float inv1 = 1.0f / l1;
    #pragma unroll
    for (int n = 0; n < 16; n++) {
        const int col = colbase + n * 8 + tq * 2;
        *(uint32_t*)(g_aoh + (rowbase + row0) * DIMV + col) =
            pack_h2(o[n][0] * inv0, o[n][1] * inv0);
        *(uint32_t*)(g_aoh + (rowbase + row0 + 8) * DIMV + col) =
            pack_h2(o[n][2] * inv1, o[n][3] * inv1);
    }
}

// ---------------------------------------------------------------------------
extern "C" void kernel_launch(void* const* d_in, const int* in_sizes, int n_in,
                              void* d_out, int out_size)
{
    const float* x  = (const float*)d_in[0];
    const float* fc = (const float*)d_in[1];
    const float* fs = (const float*)d_in[2];
    // d_in[3] = mask (causal applied analytically)
    const float* wq = (const float*)d_in[4];
    const float* wk = (const float*)d_in[5];
    const float* wv = (const float*)d_in[6];
    const float* wo = (const float*)d_in[7];
    float* out = (float*)d_out;

    cudaFuncSetAttribute(flash_hmma_kernel,
                         cudaFuncAttributeMaxDynamicSharedMemorySize, FSMEM);
    cudaFuncSetAttribute(qkv_mma_kernel,
                         cudaFuncAttributeMaxDynamicSharedMemorySize, GSMEM);
    cudaFuncSetAttribute(oproj_mma_kernel,
                         cudaFuncAttributeMaxDynamicSharedMemorySize, GSMEM);

    // 1) split inputs + weights
    split_x_kernel<<<MROWS * DIMV / 4 / 256, 256>>>(x);
    dim3 wtg(DIMV / 32, DIMV / 32, 4);
    dim3 wtb(32, 8);
    split_wT_kernel<<<wtg, wtb>>>(wq, wk, wv, wo);

    // 2) QKV projections with fused RoPE epilogue
    qkv_mma_kernel<<<dim3(DIMV / BN, MROWS / BM, 3), 256, GSMEM>>>(fc, fs);

    // 3) Causal flash attention (fp16 2-product)
    flash_hmma_kernel<<<dim3(SEQ / 128, BATCH * NH), 256, FSMEM>>>();

    // 4) output projection
    oproj_mma_kernel<<<dim3(DIMV / BN, MROWS / BM), 256, GSMEM>>>(out);
}